// round 12
// baseline (speedup 1.0000x reference)
#include <cuda_runtime.h>
#include <cuda_bf16.h>
#include <stdint.h>
#include <math.h>

// GramSchmidt: x[8,32,128,1024] fp32.
// G = X X^T per (b,c) via mma.sync bf16 (hi/lo split, 3 terms, fp32 acc),
// single-barrier software-pipelined chunks; paired-column triangular-overlay
// recurrence; Q = L X via mma.sync bf16 (pipelined); normalize per column.

#define NBC 256
#define NV  128
#define DD  1024

__device__ float g_G[NBC * NV * NV];
__device__ float g_L[NBC * NV * NV];

__device__ __forceinline__ uint32_t smem_u32(const void* p) {
    uint32_t a;
    asm("{ .reg .u64 t; cvta.to.shared.u64 t, %1; cvt.u32.u64 %0, t; }"
        : "=r"(a) : "l"(p));
    return a;
}

__device__ __forceinline__ void mma_bf16(float* d, uint32_t a0, uint32_t a1,
                                         uint32_t a2, uint32_t a3,
                                         uint32_t b0, uint32_t b1) {
    asm volatile(
        "mma.sync.aligned.m16n8k16.row.col.f32.bf16.bf16.f32 "
        "{%0,%1,%2,%3}, {%4,%5,%6,%7}, {%8,%9}, {%0,%1,%2,%3};"
        : "+f"(d[0]), "+f"(d[1]), "+f"(d[2]), "+f"(d[3])
        : "r"(a0), "r"(a1), "r"(a2), "r"(a3), "r"(b0), "r"(b1));
}

__device__ __forceinline__ void bf16_split4(float4 v, uint32_t& h01, uint32_t& h23,
                                            uint32_t& l01, uint32_t& l23) {
    __nv_bfloat16 hx = __float2bfloat16(v.x), hy = __float2bfloat16(v.y);
    __nv_bfloat16 hz = __float2bfloat16(v.z), hw = __float2bfloat16(v.w);
    __nv_bfloat16 lx = __float2bfloat16(v.x - __bfloat162float(hx));
    __nv_bfloat16 ly = __float2bfloat16(v.y - __bfloat162float(hy));
    __nv_bfloat16 lz = __float2bfloat16(v.z - __bfloat162float(hz));
    __nv_bfloat16 lw = __float2bfloat16(v.w - __bfloat162float(hw));
    h01 = ((uint32_t)__bfloat16_as_ushort(hy) << 16) | __bfloat16_as_ushort(hx);
    h23 = ((uint32_t)__bfloat16_as_ushort(hw) << 16) | __bfloat16_as_ushort(hz);
    l01 = ((uint32_t)__bfloat16_as_ushort(ly) << 16) | __bfloat16_as_ushort(lx);
    l23 = ((uint32_t)__bfloat16_as_ushort(lw) << 16) | __bfloat16_as_ushort(lz);
}

// ---------------------------------------------------------------- kernel A
// G[bc] = X X^T via HMMA bf16 hi/lo split, 3 terms (hh, hl, lh).
// Pipelined: phase ch = { LDG ch+1, MMA buf(ch&1), convert/store -> other buf },
// ONE barrier per chunk.
#define TILE_B 18432            // 128 * 144 bytes
__global__ void __launch_bounds__(256) gs_gram_mma(const float* __restrict__ X) {
    extern __shared__ __align__(16) char smc[];
    const int bc = blockIdx.x;
    const float* Xb = X + (size_t)bc * (NV * DD);
    const int t = threadIdx.x, lane = t & 31, wid = t >> 5;
    const int wm = (wid >> 2) * 64;
    const int wn = (wid & 3) * 32;
    const uint32_t sb = smem_u32(smc);

    float acc[4][4][4];
#pragma unroll
    for (int mt = 0; mt < 4; mt++)
#pragma unroll
        for (int nt = 0; nt < 4; nt++)
#pragma unroll
            for (int r = 0; r < 4; r++) acc[mt][nt][r] = 0.f;

    const uint32_t lane_a = (uint32_t)((lane >> 2) * 144 + (lane & 3) * 4);

    float4 pf[8];
    // prologue: stage chunk 0 into buf0
#pragma unroll
    for (int it = 0; it < 8; it++) {
        int fl = t + 256 * it;
        pf[it] = *(const float4*)(Xb + (fl >> 4) * DD + (fl & 15) * 4);
    }
#pragma unroll
    for (int it = 0; it < 8; it++) {
        int fl = t + 256 * it;
        int r = fl >> 4, c4 = fl & 15;
        uint32_t h01, h23, l01, l23;
        bf16_split4(pf[it], h01, h23, l01, l23);
        uint32_t off = (uint32_t)(r * 144 + c4 * 8);
        asm volatile("st.shared.v2.b32 [%0], {%1,%2};"
                     :: "r"(sb + off), "r"(h01), "r"(h23) : "memory");
        asm volatile("st.shared.v2.b32 [%0], {%1,%2};"
                     :: "r"(sb + TILE_B + off), "r"(l01), "r"(l23) : "memory");
    }
    __syncthreads();

    for (int ch = 0; ch < 16; ch++) {
        const uint32_t hi_s = sb + (uint32_t)(ch & 1) * (2 * TILE_B);
        const uint32_t lo_s = hi_s + TILE_B;
        if (ch + 1 < 16) {
#pragma unroll
            for (int it = 0; it < 8; it++) {
                int fl = t + 256 * it;
                pf[it] = *(const float4*)(Xb + (fl >> 4) * DD + (ch + 1) * 64 + (fl & 15) * 4);
            }
        }

#pragma unroll
        for (int ks = 0; ks < 4; ks++) {
            const uint32_t kb = (uint32_t)(ks * 32);
            uint32_t Ah[4][4], Al[4][4], Bh[4][2], Bl[4][2];
#pragma unroll
            for (int mt = 0; mt < 4; mt++) {
                uint32_t ah = hi_s + (uint32_t)((wm + mt * 16) * 144) + kb + lane_a;
                uint32_t al = lo_s + (uint32_t)((wm + mt * 16) * 144) + kb + lane_a;
                asm volatile("ld.shared.b32 %0, [%1];"       : "=r"(Ah[mt][0]) : "r"(ah));
                asm volatile("ld.shared.b32 %0, [%1+1152];"  : "=r"(Ah[mt][1]) : "r"(ah));
                asm volatile("ld.shared.b32 %0, [%1+16];"    : "=r"(Ah[mt][2]) : "r"(ah));
                asm volatile("ld.shared.b32 %0, [%1+1168];"  : "=r"(Ah[mt][3]) : "r"(ah));
                asm volatile("ld.shared.b32 %0, [%1];"       : "=r"(Al[mt][0]) : "r"(al));
                asm volatile("ld.shared.b32 %0, [%1+1152];"  : "=r"(Al[mt][1]) : "r"(al));
                asm volatile("ld.shared.b32 %0, [%1+16];"    : "=r"(Al[mt][2]) : "r"(al));
                asm volatile("ld.shared.b32 %0, [%1+1168];"  : "=r"(Al[mt][3]) : "r"(al));
            }
#pragma unroll
            for (int nt = 0; nt < 4; nt++) {
                uint32_t bh = hi_s + (uint32_t)((wn + nt * 8) * 144) + kb + lane_a;
                uint32_t bl = lo_s + (uint32_t)((wn + nt * 8) * 144) + kb + lane_a;
                asm volatile("ld.shared.b32 %0, [%1];"    : "=r"(Bh[nt][0]) : "r"(bh));
                asm volatile("ld.shared.b32 %0, [%1+16];" : "=r"(Bh[nt][1]) : "r"(bh));
                asm volatile("ld.shared.b32 %0, [%1];"    : "=r"(Bl[nt][0]) : "r"(bl));
                asm volatile("ld.shared.b32 %0, [%1+16];" : "=r"(Bl[nt][1]) : "r"(bl));
            }
#pragma unroll
            for (int mt = 0; mt < 4; mt++)
#pragma unroll
                for (int nt = 0; nt < 4; nt++) {
                    mma_bf16(acc[mt][nt], Ah[mt][0], Ah[mt][1], Ah[mt][2], Ah[mt][3],
                             Bh[nt][0], Bh[nt][1]);
                    mma_bf16(acc[mt][nt], Ah[mt][0], Ah[mt][1], Ah[mt][2], Ah[mt][3],
                             Bl[nt][0], Bl[nt][1]);
                    mma_bf16(acc[mt][nt], Al[mt][0], Al[mt][1], Al[mt][2], Al[mt][3],
                             Bh[nt][0], Bh[nt][1]);
                }
        }

        if (ch + 1 < 16) {
            const uint32_t nhi = sb + (uint32_t)((ch + 1) & 1) * (2 * TILE_B);
            const uint32_t nlo = nhi + TILE_B;
#pragma unroll
            for (int it = 0; it < 8; it++) {
                int fl = t + 256 * it;
                int r = fl >> 4, c4 = fl & 15;
                uint32_t h01, h23, l01, l23;
                bf16_split4(pf[it], h01, h23, l01, l23);
                uint32_t off = (uint32_t)(r * 144 + c4 * 8);
                asm volatile("st.shared.v2.b32 [%0], {%1,%2};"
                             :: "r"(nhi + off), "r"(h01), "r"(h23) : "memory");
                asm volatile("st.shared.v2.b32 [%0], {%1,%2};"
                             :: "r"(nlo + off), "r"(l01), "r"(l23) : "memory");
            }
        }
        __syncthreads();
    }

    float* Gb = g_G + (size_t)bc * (NV * NV);
#pragma unroll
    for (int mt = 0; mt < 4; mt++) {
        int row = wm + mt * 16 + (lane >> 2);
#pragma unroll
        for (int nt = 0; nt < 4; nt++) {
            int col = wn + nt * 8 + (lane & 3) * 2;
            *(float2*)(Gb + row * NV + col)       = make_float2(acc[mt][nt][0], acc[mt][nt][1]);
            *(float2*)(Gb + (row + 8) * NV + col) = make_float2(acc[mt][nt][2], acc[mt][nt][3]);
        }
    }
}

// ---------------------------------------------------------------- kernel B
// Paired-column triangular-overlay recurrence (unchanged, Round-11).
__global__ void gs_chol_kernel() {
    extern __shared__ float M[];                // 128 x 129
    float* cf1 = M + NV * 129;
    float* cf2 = cf1 + NV;
    float* pub = cf2 + NV;

    const int bc = blockIdx.x;
    const int t  = threadIdx.x;
    const int w0 = t & ~31;
    const float* Gb = g_G + (size_t)bc * (NV * NV);

#pragma unroll
    for (int it = 0; it < 129; it++) M[it * 128 + t] = 0.f;
    cf1[t] = 0.f; cf2[t] = 0.f;
    __syncthreads();

    float invnn = 1.f;
    float g0 = Gb[t];
    M[t] = g0;
    if (t == 0) { invnn = 1.f / g0; }
    __syncthreads();

    {
        float g1 = Gb[NV + t];
        if (t == 0) pub[0] = M[1] * invnn;
        __syncthreads();
        float cf = pub[0];
        float v = (t >= 1) ? (g1 - cf * M[t]) : -cf;
        M[129 + t] = v;
        if (t == 1) invnn = 1.f / v;
        __syncthreads();
    }

    for (int i = 2; i < NV; i += 2) {
        float g1 = Gb[i * NV + t];
        float g2 = Gb[(i + 1) * NV + t];

        float c1 = (t < i) ? M[t * 129 + i] * invnn : 0.f;
        float c2 = (t < i) ? M[t * 129 + i + 1] * invnn : 0.f;
        cf1[t] = c1; cf2[t] = c2;
        __syncthreads();

        float a1, a2;
        if (w0 >= i + 1) {
            float p0 = g1, p1 = 0.f, q0 = g2, q1 = 0.f;
            const int jmax = (i + 3) & ~3;
            for (int j0 = 0; j0 < jmax; j0 += 4) {
                float4 f1 = *(const float4*)(cf1 + j0);
                float4 f2 = *(const float4*)(cf2 + j0);
                float m0 = M[(j0 + 0) * 129 + t];
                float m1 = M[(j0 + 1) * 129 + t];
                float m2 = M[(j0 + 2) * 129 + t];
                float m3 = M[(j0 + 3) * 129 + t];
                p0 -= f1.x * m0; q0 -= f2.x * m0;
                p1 -= f1.y * m1; q1 -= f2.y * m1;
                p0 -= f1.z * m2; q0 -= f2.z * m2;
                p1 -= f1.w * m3; q1 -= f2.w * m3;
            }
            a1 = p0 + p1; a2 = q0 + q1;
        } else if (w0 + 32 <= i) {
            float p0 = -c1, p1 = 0.f, q0 = -c2, q1 = 0.f;
#pragma unroll
            for (int j = 0; j < 32; j += 2) {
                int jj = w0 + j;
                float u0 = M[(jj + 0) * 129 + t];
                float u1 = M[(jj + 1) * 129 + t];
                float f10 = (jj + 0 > t) ? cf1[jj + 0] : 0.f;
                float f20 = (jj + 0 > t) ? cf2[jj + 0] : 0.f;
                float f11 = (jj + 1 > t) ? cf1[jj + 1] : 0.f;
                float f21 = (jj + 1 > t) ? cf2[jj + 1] : 0.f;
                p0 -= f10 * u0; q0 -= f20 * u0;
                p1 -= f11 * u1; q1 -= f21 * u1;
            }
            const int jmax = (i + 3) & ~3;
            for (int j0 = w0 + 32; j0 < jmax; j0 += 4) {
                float4 f1 = *(const float4*)(cf1 + j0);
                float4 f2 = *(const float4*)(cf2 + j0);
                float m0 = M[(j0 + 0) * 129 + t];
                float m1 = M[(j0 + 1) * 129 + t];
                float m2 = M[(j0 + 2) * 129 + t];
                float m3 = M[(j0 + 3) * 129 + t];
                p0 -= f1.x * m0; q0 -= f2.x * m0;
                p1 -= f1.y * m1; q1 -= f2.y * m1;
                p0 -= f1.z * m2; q0 -= f2.z * m2;
                p1 -= f1.w * m3; q1 -= f2.w * m3;
            }
            a1 = p0 + p1; a2 = q0 + q1;
        } else {
            a1 = (t >= i) ? g1 : -c1;
            a2 = (t > i)  ? g2 : ((t == i) ? 0.f : -c2);
            for (int j = 0; j < i; j++) {
                float m = M[j * 129 + t];
                float f1 = ((t >= i) || (j > t)) ? cf1[j] : 0.f;
                float f2 = ((t > i)  || (j > t)) ? cf2[j] : 0.f;
                a1 -= f1 * m;
                a2 -= f2 * m;
            }
        }

        M[i * 129 + t] = a1;
        if (t == i)     { invnn = 1.f / a1; pub[0] = invnn; }
        if (t == i + 1) { pub[1] = a1; }
        __syncthreads();

        float cf2i = pub[1] * pub[0];
        a2 -= cf2i * ((t == i) ? 1.f : a1);
        M[(i + 1) * 129 + t] = a2;
        if (t == i + 1) invnn = 1.f / a2;
        __syncthreads();
    }

    float* Lb = g_L + (size_t)bc * (NV * NV);
#pragma unroll 4
    for (int r = 0; r < NV; r++) {
        float v = (t < r) ? M[r * 129 + t] : ((t == r) ? 1.f : 0.f);
        Lb[r * NV + t] = v;
    }
}

// ---------------------------------------------------------------- kernel C
// Q = L @ Xchunk via HMMA bf16, pipelined with double-buffered smem:
// stage0 -> BAR -> { LDG chunk1, MMA chunk0, convert/store chunk1 } -> BAR
// -> MMA chunk1 -> epilogue (colsumsq over N, scale, store).
#define LT 18432                // 128 * 144 B  (L tile, 64 k)
#define XT 17408                // 64 * 272 B   (X tile, 128 d)
#define CHB (2 * LT + 2 * XT)   // 71680 per chunk
__global__ void __launch_bounds__(256) gs_apply_mma(const float* __restrict__ X,
                                                   float* __restrict__ out) {
    extern __shared__ __align__(16) char smc[];
    const int bc = blockIdx.x >> 3;
    const int dc = blockIdx.x & 7;
    const int t = threadIdx.x, lane = t & 31, wid = t >> 5;
    const int wp = wid >> 2;
    const int wn = (wid & 3) * 32;
    const uint32_t sb = smem_u32(smc);

    const float* Xb = X + (size_t)bc * (NV * DD) + dc * 128;
    const float* Lb = g_L + (size_t)bc * (NV * NV);

    float acc[4][4][4];
#pragma unroll
    for (int mt = 0; mt < 4; mt++)
#pragma unroll
        for (int nt = 0; nt < 4; nt++)
#pragma unroll
            for (int r = 0; r < 4; r++) acc[mt][nt][r] = 0.f;

    const uint32_t lane_a = (uint32_t)((lane >> 2) * 144 + (lane & 3) * 4);
    const int brow = (lane & 7) + (lane & 8);
    const int bcol = wn + ((lane >> 4) << 3);

    // stage chunk 0 into buf0
    {
        const uint32_t Lh = sb, Ll = sb + LT, Xh = sb + 2 * LT, Xl = sb + 2 * LT + XT;
#pragma unroll
        for (int it = 0; it < 8; it++) {
            int fl = t + 256 * it;
            int r = fl >> 4, c4 = fl & 15;
            float4 v = *(const float4*)(Lb + r * NV + c4 * 4);
            uint32_t h01, h23, l01, l23;
            bf16_split4(v, h01, h23, l01, l23);
            uint32_t off = (uint32_t)(r * 144 + c4 * 8);
            asm volatile("st.shared.v2.b32 [%0], {%1,%2};"
                         :: "r"(Lh + off), "r"(h01), "r"(h23) : "memory");
            asm volatile("st.shared.v2.b32 [%0], {%1,%2};"
                         :: "r"(Ll + off), "r"(l01), "r"(l23) : "memory");
        }
#pragma unroll
        for (int it = 0; it < 8; it++) {
            int fl = t + 256 * it;
            int r = fl >> 5, c4 = fl & 31;
            float4 v = *(const float4*)(Xb + r * DD + c4 * 4);
            uint32_t h01, h23, l01, l23;
            bf16_split4(v, h01, h23, l01, l23);
            uint32_t off = (uint32_t)(r * 272 + c4 * 8);
            asm volatile("st.shared.v2.b32 [%0], {%1,%2};"
                         :: "r"(Xh + off), "r"(h01), "r"(h23) : "memory");
            asm volatile("st.shared.v2.b32 [%0], {%1,%2};"
                         :: "r"(Xl + off), "r"(l01), "r"(l23) : "memory");
        }
    }
    __syncthreads();

    float4 pfL[8], pfX[8];

    for (int ch = 0; ch < 2; ch++) {
        const uint32_t cb = sb + (uint32_t)ch * CHB;
        const uint32_t Lh = cb, Ll = cb + LT, Xh = cb + 2 * LT, Xl = cb + 2 * LT + XT;

        if (ch == 0) {               // prefetch chunk 1 (latency under MMA)
#pragma unroll
            for (int it = 0; it < 8; it++) {
                int fl = t + 256 * it;
                pfL[it] = *(const float4*)(Lb + (fl >> 4) * NV + 64 + (fl & 15) * 4);
            }
#pragma unroll
            for (int it = 0; it < 8; it++) {
                int fl = t + 256 * it;
                pfX[it] = *(const float4*)(Xb + (64 + (fl >> 5)) * DD + (fl & 31) * 4);
            }
        }

#pragma unroll
        for (int ks = 0; ks < 4; ks++) {
            const int kg = ch * 4 + ks;
            uint32_t Bh[4][2], Bl[4][2];
#pragma unroll
            for (int nb2 = 0; nb2 < 2; nb2++) {
                uint32_t ba = (uint32_t)((ks * 16 + brow) * 272 + (bcol + nb2 * 16) * 2);
                uint32_t r0, r1, r2, r3;
                asm volatile("ldmatrix.sync.aligned.m8n8.x4.trans.shared.b16 "
                             "{%0,%1,%2,%3}, [%4];"
                             : "=r"(r0), "=r"(r1), "=r"(r2), "=r"(r3) : "r"(Xh + ba));
                Bh[nb2 * 2][0] = r0; Bh[nb2 * 2][1] = r1;
                Bh[nb2 * 2 + 1][0] = r2; Bh[nb2 * 2 + 1][1] = r3;
                asm volatile("ldmatrix.sync.aligned.m8n8.x4.trans.shared.b16 "
                             "{%0,%1,%2,%3}, [%4];"
                             : "=r"(r0), "=r"(r1), "=r"(r2), "=r"(r3) : "r"(Xl + ba));
                Bl[nb2 * 2][0] = r0; Bl[nb2 * 2][1] = r1;
                Bl[nb2 * 2 + 1][0] = r2; Bl[nb2 * 2 + 1][1] = r3;
            }
#pragma unroll
            for (int mt = 0; mt < 4; mt++) {
                if (kg <= 2 * mt + wp) {
                    uint32_t ah = Lh + (uint32_t)((2 * mt + wp) * 2304 + ks * 32) + lane_a;
                    uint32_t al = Ll + (uint32_t)((2 * mt + wp) * 2304 + ks * 32) + lane_a;
                    uint32_t A0, A1, A2, A3, a0, a1, a2, a3;
                    asm volatile("ld.shared.b32 %0, [%1];"      : "=r"(A0) : "r"(ah));
                    asm volatile("ld.shared.b32 %0, [%1+1152];" : "=r"(A1) : "r"(ah));
                    asm volatile("ld.shared.b32 %0, [%1+16];"   : "=r"(A2) : "r"(ah));
                    asm volatile("ld.shared.b32 %0, [%1+1168];" : "=r"(A3) : "r"(ah));
                    asm volatile("ld.shared.b32 %0, [%1];"      : "=r"(a0) : "r"(al));
                    asm volatile("ld.shared.b32 %0, [%1+1152];" : "=r"(a1) : "r"(al));
                    asm volatile("ld.shared.b32 %0, [%1+16];"   : "=r"(a2) : "r"(al));
                    asm volatile("ld.shared.b32 %0, [%1+1168];" : "=r"(a3) : "r"(al));
#pragma unroll
                    for (int nt = 0; nt < 4; nt++) {
                        mma_bf16(acc[mt][nt], A0, A1, A2, A3, Bh[nt][0], Bh[nt][1]);
                        mma_bf16(acc[mt][nt], A0, A1, A2, A3, Bl[nt][0], Bl[nt][1]);
                        mma_bf16(acc[mt][nt], a0, a1, a2, a3, Bh[nt][0], Bh[nt][1]);
                    }
                }
            }
        }

        if (ch == 0) {               // convert/store chunk 1 into buf1 (overlaps tensor drain)
            const uint32_t nLh = sb + CHB, nLl = nLh + LT;
            const uint32_t nXh = nLh + 2 * LT, nXl = nXh + XT;
#pragma unroll
            for (int it = 0; it < 8; it++) {
                int fl = t + 256 * it;
                int r = fl >> 4, c4 = fl & 15;
                uint32_t h01, h23, l01, l23;
                bf16_split4(pfL[it], h01, h23, l01, l23);
                uint32_t off = (uint32_t)(r * 144 + c4 * 8);
                asm volatile("st.shared.v2.b32 [%0], {%1,%2};"
                             :: "r"(nLh + off), "r"(h01), "r"(h23) : "memory");
                asm volatile("st.shared.v2.b32 [%0], {%1,%2};"
                             :: "r"(nLl + off), "r"(l01), "r"(l23) : "memory");
            }
#pragma unroll
            for (int it = 0; it < 8; it++) {
                int fl = t + 256 * it;
                int r = fl >> 5, c4 = fl & 31;
                uint32_t h01, h23, l01, l23;
                bf16_split4(pfX[it], h01, h23, l01, l23);
                uint32_t off = (uint32_t)(r * 272 + c4 * 8);
                asm volatile("st.shared.v2.b32 [%0], {%1,%2};"
                             :: "r"(nXh + off), "r"(h01), "r"(h23) : "memory");
                asm volatile("st.shared.v2.b32 [%0], {%1,%2};"
                             :: "r"(nXl + off), "r"(l01), "r"(l23) : "memory");
            }
        }
        __syncthreads();
    }

    // epilogue: stage Q, column norms over N, scale, store
    float* Qs = (float*)smc;                 // 128 x 132 fp32
    float* rn = Qs + 128 * 132;
#pragma unroll
    for (int mt = 0; mt < 4; mt++) {
        int row = (2 * mt + wp) * 16 + (lane >> 2);
#pragma unroll
        for (int nt = 0; nt < 4; nt++) {
            int col = wn + nt * 8 + (lane & 3) * 2;
            *(float2*)(Qs + row * 132 + col)       = make_float2(acc[mt][nt][0], acc[mt][nt][1]);
            *(float2*)(Qs + (row + 8) * 132 + col) = make_float2(acc[mt][nt][2], acc[mt][nt][3]);
        }
    }
    __syncthreads();

    if (t < 128) {
        float s = 0.f;
#pragma unroll 4
        for (int i = 0; i < 128; i++) { float q = Qs[i * 132 + t]; s += q * q; }
        rn[t] = rsqrtf(s);
    }
    __syncthreads();

    float* ob = out + (size_t)bc * (NV * DD) + dc * 128;
#pragma unroll
    for (int it = 0; it < 16; it++) {
        int fl = t + 256 * it;
        int r = fl >> 5, c4 = fl & 31;
        float4 q = *(float4*)(Qs + r * 132 + c4 * 4);
        q.x *= rn[c4 * 4 + 0];
        q.y *= rn[c4 * 4 + 1];
        q.z *= rn[c4 * 4 + 2];
        q.w *= rn[c4 * 4 + 3];
        *(float4*)(ob + r * DD + c4 * 4) = q;
    }
}

// ---------------------------------------------------------------- launcher
extern "C" void kernel_launch(void* const* d_in, const int* in_sizes, int n_in,
                              void* d_out, int out_size) {
    const float* x = (const float*)d_in[0];
    float* out = (float*)d_out;

    const int smA = 4 * TILE_B;                                         // 73728
    const int smB = (NV * 129 + 2 * NV + 8) * (int)sizeof(float);       // 67104
    const int smC = 2 * CHB;                                            // 143360

    cudaFuncSetAttribute(gs_gram_mma,    cudaFuncAttributeMaxDynamicSharedMemorySize, smA);
    cudaFuncSetAttribute(gs_chol_kernel, cudaFuncAttributeMaxDynamicSharedMemorySize, smB);
    cudaFuncSetAttribute(gs_apply_mma,   cudaFuncAttributeMaxDynamicSharedMemorySize, smC);

    gs_gram_mma<<<NBC, 256, smA>>>(x);
    gs_chol_kernel<<<NBC, 128, smB>>>();
    gs_apply_mma<<<NBC * 8, 256, smC>>>(x, out);
}

// round 13
// speedup vs baseline: 1.1361x; 1.1361x over previous
#include <cuda_runtime.h>
#include <cuda_bf16.h>
#include <stdint.h>
#include <math.h>

// GramSchmidt: x[8,32,128,1024] fp32.
// G = X X^T per (b,c) via mma.sync bf16 (hi/lo split, 3 terms, fp32 acc);
// 4-column blocked triangular-overlay recurrence; Q = L X via mma.sync bf16;
// out = Q * rsqrt(colsumsq_over_N(Q)).

#define NBC 256
#define NV  128
#define DD  1024

__device__ float g_G[NBC * NV * NV];
__device__ float g_L[NBC * NV * NV];

__device__ __forceinline__ uint32_t smem_u32(const void* p) {
    uint32_t a;
    asm("{ .reg .u64 t; cvta.to.shared.u64 t, %1; cvt.u32.u64 %0, t; }"
        : "=r"(a) : "l"(p));
    return a;
}

__device__ __forceinline__ void mma_bf16(float* d, uint32_t a0, uint32_t a1,
                                         uint32_t a2, uint32_t a3,
                                         uint32_t b0, uint32_t b1) {
    asm volatile(
        "mma.sync.aligned.m16n8k16.row.col.f32.bf16.bf16.f32 "
        "{%0,%1,%2,%3}, {%4,%5,%6,%7}, {%8,%9}, {%0,%1,%2,%3};"
        : "+f"(d[0]), "+f"(d[1]), "+f"(d[2]), "+f"(d[3])
        : "r"(a0), "r"(a1), "r"(a2), "r"(a3), "r"(b0), "r"(b1));
}

__device__ __forceinline__ void bf16_split4(float4 v, uint32_t& h01, uint32_t& h23,
                                            uint32_t& l01, uint32_t& l23) {
    __nv_bfloat16 hx = __float2bfloat16(v.x), hy = __float2bfloat16(v.y);
    __nv_bfloat16 hz = __float2bfloat16(v.z), hw = __float2bfloat16(v.w);
    __nv_bfloat16 lx = __float2bfloat16(v.x - __bfloat162float(hx));
    __nv_bfloat16 ly = __float2bfloat16(v.y - __bfloat162float(hy));
    __nv_bfloat16 lz = __float2bfloat16(v.z - __bfloat162float(hz));
    __nv_bfloat16 lw = __float2bfloat16(v.w - __bfloat162float(hw));
    h01 = ((uint32_t)__bfloat16_as_ushort(hy) << 16) | __bfloat16_as_ushort(hx);
    h23 = ((uint32_t)__bfloat16_as_ushort(hw) << 16) | __bfloat16_as_ushort(hz);
    l01 = ((uint32_t)__bfloat16_as_ushort(ly) << 16) | __bfloat16_as_ushort(lx);
    l23 = ((uint32_t)__bfloat16_as_ushort(lw) << 16) | __bfloat16_as_ushort(lz);
}

// ---------------------------------------------------------------- kernel A
// G[bc] = X X^T via HMMA bf16 hi/lo split, 3 terms. Pipelined, 1 BAR/chunk.
#define TILE_B 18432            // 128 * 144 bytes
__global__ void __launch_bounds__(256) gs_gram_mma(const float* __restrict__ X) {
    extern __shared__ __align__(16) char smc[];
    const int bc = blockIdx.x;
    const float* Xb = X + (size_t)bc * (NV * DD);
    const int t = threadIdx.x, lane = t & 31, wid = t >> 5;
    const int wm = (wid >> 2) * 64;
    const int wn = (wid & 3) * 32;
    const uint32_t sb = smem_u32(smc);

    float acc[4][4][4];
#pragma unroll
    for (int mt = 0; mt < 4; mt++)
#pragma unroll
        for (int nt = 0; nt < 4; nt++)
#pragma unroll
            for (int r = 0; r < 4; r++) acc[mt][nt][r] = 0.f;

    const uint32_t lane_a = (uint32_t)((lane >> 2) * 144 + (lane & 3) * 4);

    float4 pf[8];
#pragma unroll
    for (int it = 0; it < 8; it++) {
        int fl = t + 256 * it;
        pf[it] = *(const float4*)(Xb + (fl >> 4) * DD + (fl & 15) * 4);
    }
#pragma unroll
    for (int it = 0; it < 8; it++) {
        int fl = t + 256 * it;
        int r = fl >> 4, c4 = fl & 15;
        uint32_t h01, h23, l01, l23;
        bf16_split4(pf[it], h01, h23, l01, l23);
        uint32_t off = (uint32_t)(r * 144 + c4 * 8);
        asm volatile("st.shared.v2.b32 [%0], {%1,%2};"
                     :: "r"(sb + off), "r"(h01), "r"(h23) : "memory");
        asm volatile("st.shared.v2.b32 [%0], {%1,%2};"
                     :: "r"(sb + TILE_B + off), "r"(l01), "r"(l23) : "memory");
    }
    __syncthreads();

    for (int ch = 0; ch < 16; ch++) {
        const uint32_t hi_s = sb + (uint32_t)(ch & 1) * (2 * TILE_B);
        const uint32_t lo_s = hi_s + TILE_B;
        if (ch + 1 < 16) {
#pragma unroll
            for (int it = 0; it < 8; it++) {
                int fl = t + 256 * it;
                pf[it] = *(const float4*)(Xb + (fl >> 4) * DD + (ch + 1) * 64 + (fl & 15) * 4);
            }
        }

#pragma unroll
        for (int ks = 0; ks < 4; ks++) {
            const uint32_t kb = (uint32_t)(ks * 32);
            uint32_t Ah[4][4], Al[4][4], Bh[4][2], Bl[4][2];
#pragma unroll
            for (int mt = 0; mt < 4; mt++) {
                uint32_t ah = hi_s + (uint32_t)((wm + mt * 16) * 144) + kb + lane_a;
                uint32_t al = lo_s + (uint32_t)((wm + mt * 16) * 144) + kb + lane_a;
                asm volatile("ld.shared.b32 %0, [%1];"       : "=r"(Ah[mt][0]) : "r"(ah));
                asm volatile("ld.shared.b32 %0, [%1+1152];"  : "=r"(Ah[mt][1]) : "r"(ah));
                asm volatile("ld.shared.b32 %0, [%1+16];"    : "=r"(Ah[mt][2]) : "r"(ah));
                asm volatile("ld.shared.b32 %0, [%1+1168];"  : "=r"(Ah[mt][3]) : "r"(ah));
                asm volatile("ld.shared.b32 %0, [%1];"       : "=r"(Al[mt][0]) : "r"(al));
                asm volatile("ld.shared.b32 %0, [%1+1152];"  : "=r"(Al[mt][1]) : "r"(al));
                asm volatile("ld.shared.b32 %0, [%1+16];"    : "=r"(Al[mt][2]) : "r"(al));
                asm volatile("ld.shared.b32 %0, [%1+1168];"  : "=r"(Al[mt][3]) : "r"(al));
            }
#pragma unroll
            for (int nt = 0; nt < 4; nt++) {
                uint32_t bh = hi_s + (uint32_t)((wn + nt * 8) * 144) + kb + lane_a;
                uint32_t bl = lo_s + (uint32_t)((wn + nt * 8) * 144) + kb + lane_a;
                asm volatile("ld.shared.b32 %0, [%1];"    : "=r"(Bh[nt][0]) : "r"(bh));
                asm volatile("ld.shared.b32 %0, [%1+16];" : "=r"(Bh[nt][1]) : "r"(bh));
                asm volatile("ld.shared.b32 %0, [%1];"    : "=r"(Bl[nt][0]) : "r"(bl));
                asm volatile("ld.shared.b32 %0, [%1+16];" : "=r"(Bl[nt][1]) : "r"(bl));
            }
#pragma unroll
            for (int mt = 0; mt < 4; mt++)
#pragma unroll
                for (int nt = 0; nt < 4; nt++) {
                    mma_bf16(acc[mt][nt], Ah[mt][0], Ah[mt][1], Ah[mt][2], Ah[mt][3],
                             Bh[nt][0], Bh[nt][1]);
                    mma_bf16(acc[mt][nt], Ah[mt][0], Ah[mt][1], Ah[mt][2], Ah[mt][3],
                             Bl[nt][0], Bl[nt][1]);
                    mma_bf16(acc[mt][nt], Al[mt][0], Al[mt][1], Al[mt][2], Al[mt][3],
                             Bh[nt][0], Bh[nt][1]);
                }
        }

        if (ch + 1 < 16) {
            const uint32_t nhi = sb + (uint32_t)((ch + 1) & 1) * (2 * TILE_B);
            const uint32_t nlo = nhi + TILE_B;
#pragma unroll
            for (int it = 0; it < 8; it++) {
                int fl = t + 256 * it;
                int r = fl >> 4, c4 = fl & 15;
                uint32_t h01, h23, l01, l23;
                bf16_split4(pf[it], h01, h23, l01, l23);
                uint32_t off = (uint32_t)(r * 144 + c4 * 8);
                asm volatile("st.shared.v2.b32 [%0], {%1,%2};"
                             :: "r"(nhi + off), "r"(h01), "r"(h23) : "memory");
                asm volatile("st.shared.v2.b32 [%0], {%1,%2};"
                             :: "r"(nlo + off), "r"(l01), "r"(l23) : "memory");
            }
        }
        __syncthreads();
    }

    float* Gb = g_G + (size_t)bc * (NV * NV);
#pragma unroll
    for (int mt = 0; mt < 4; mt++) {
        int row = wm + mt * 16 + (lane >> 2);
#pragma unroll
        for (int nt = 0; nt < 4; nt++) {
            int col = wn + nt * 8 + (lane & 3) * 2;
            *(float2*)(Gb + row * NV + col)       = make_float2(acc[mt][nt][0], acc[mt][nt][1]);
            *(float2*)(Gb + (row + 8) * NV + col) = make_float2(acc[mt][nt][2], acc[mt][nt][3]);
        }
    }
}

// ---------------------------------------------------------------- kernel B
// 4-column blocked triangular-overlay recurrence.
// Rows i..i+3 share ONE pass over M[j][t] (j<i): 4 FMA per M load.
// Within-block couplings completed from registers via published scalars:
// mult for row j at thread t = (t==j ? 1 : (i<t<r ? 0 : a_j)).
__global__ void gs_chol_kernel() {
    extern __shared__ float M[];                // 128 x 129
    float* cf0 = M + NV * 129;                  // 4 x 128 coef vectors
    float* cf1v = cf0 + NV;
    float* cf2v = cf1v + NV;
    float* cf3v = cf2v + NV;
    float* pub = cf3v + NV;                     // 16

    const int bc = blockIdx.x;
    const int t  = threadIdx.x;
    const int w0 = t & ~31;
    const float* Gb = g_G + (size_t)bc * (NV * NV);

#pragma unroll
    for (int it = 0; it < 129; it++) M[it * 128 + t] = 0.f;
    cf0[t] = 0.f; cf1v[t] = 0.f; cf2v[t] = 0.f; cf3v[t] = 0.f;
    __syncthreads();

    float invnn = 1.f;
    // row 0
    float g0 = Gb[t];
    M[t] = g0;
    if (t == 0) invnn = 1.f / g0;
    __syncthreads();
    // row 1
    {
        float g1 = Gb[NV + t];
        if (t == 0) pub[0] = M[1] * invnn;
        __syncthreads();
        float cf = pub[0];
        float v = (t >= 1) ? (g1 - cf * M[t]) : -cf;
        M[129 + t] = v;
        if (t == 1) invnn = 1.f / v;
        __syncthreads();
    }
    // pair i=2 (rows 2,3) — R11 pair body
    {
        const int i = 2;
        float g1 = Gb[i * NV + t];
        float g2 = Gb[(i + 1) * NV + t];
        float c1 = (t < i) ? M[t * 129 + i] * invnn : 0.f;
        float c2 = (t < i) ? M[t * 129 + i + 1] * invnn : 0.f;
        cf0[t] = c1; cf1v[t] = c2;
        __syncthreads();

        float a1, a2;
        {   // straddle-style (i=2 small; only low warp matters but uniform is fine)
            a1 = (t >= i) ? g1 : -c1;
            a2 = (t > i)  ? g2 : ((t == i) ? 0.f : -c2);
            for (int j = 0; j < i; j++) {
                float m = M[j * 129 + t];
                float f1 = ((t >= i) || (j > t)) ? cf0[j] : 0.f;
                float f2 = ((t > i)  || (j > t)) ? cf1v[j] : 0.f;
                a1 -= f1 * m;
                a2 -= f2 * m;
            }
        }
        M[i * 129 + t] = a1;
        if (t == i)     { invnn = 1.f / a1; pub[0] = invnn; }
        if (t == i + 1) { pub[1] = a1; }
        __syncthreads();
        float cf2i = pub[1] * pub[0];
        a2 -= cf2i * ((t == i) ? 1.f : a1);
        M[(i + 1) * 129 + t] = a2;
        if (t == i + 1) invnn = 1.f / a2;
        __syncthreads();
    }

    // 4-blocks i = 4, 8, ..., 124  (i % 4 == 0 -> jmax == i exactly)
    for (int i = 4; i < NV; i += 4) {
        float gg0 = Gb[(i + 0) * NV + t];
        float gg1 = Gb[(i + 1) * NV + t];
        float gg2 = Gb[(i + 2) * NV + t];
        float gg3 = Gb[(i + 3) * NV + t];

        float c0 = 0.f, c1 = 0.f, c2 = 0.f, c3 = 0.f;
        if (t < i) {
            const float* Mr = M + t * 129 + i;
            c0 = Mr[0] * invnn; c1 = Mr[1] * invnn;
            c2 = Mr[2] * invnn; c3 = Mr[3] * invnn;
        }
        cf0[t] = c0; cf1v[t] = c1; cf2v[t] = c2; cf3v[t] = c3;
        __syncthreads();

        float a0, a1, a2, a3;
        if (w0 > i + 3) {
            // pure P: all t >= i+4
            float p0 = gg0, p1 = gg1, p2 = gg2, p3 = gg3;
            for (int j0 = 0; j0 < i; j0 += 4) {
                float4 f0 = *(const float4*)(cf0 + j0);
                float4 f1 = *(const float4*)(cf1v + j0);
                float4 f2 = *(const float4*)(cf2v + j0);
                float4 f3 = *(const float4*)(cf3v + j0);
                float m0 = M[(j0 + 0) * 129 + t];
                float m1 = M[(j0 + 1) * 129 + t];
                float m2 = M[(j0 + 2) * 129 + t];
                float m3 = M[(j0 + 3) * 129 + t];
                p0 -= f0.x * m0 + f0.y * m1 + f0.z * m2 + f0.w * m3;
                p1 -= f1.x * m0 + f1.y * m1 + f1.z * m2 + f1.w * m3;
                p2 -= f2.x * m0 + f2.y * m1 + f2.z * m2 + f2.w * m3;
                p3 -= f3.x * m0 + f3.y * m1 + f3.z * m2 + f3.w * m3;
            }
            a0 = p0; a1 = p1; a2 = p2; a3 = p3;
        } else if (w0 + 32 <= i) {
            // pure L: all t < i; chunks below w0 all excluded (j < t)
            float p0 = -c0, p1 = -c1, p2 = -c2, p3 = -c3;
#pragma unroll
            for (int j = 0; j < 32; j += 2) {
                int jj = w0 + j;
                float m0 = M[(jj + 0) * 129 + t];
                float m1 = M[(jj + 1) * 129 + t];
                bool s0 = (jj + 0 > t), s1 = (jj + 1 > t);
                p0 -= (s0 ? cf0[jj] : 0.f) * m0 + (s1 ? cf0[jj + 1] : 0.f) * m1;
                p1 -= (s0 ? cf1v[jj] : 0.f) * m0 + (s1 ? cf1v[jj + 1] : 0.f) * m1;
                p2 -= (s0 ? cf2v[jj] : 0.f) * m0 + (s1 ? cf2v[jj + 1] : 0.f) * m1;
                p3 -= (s0 ? cf3v[jj] : 0.f) * m0 + (s1 ? cf3v[jj + 1] : 0.f) * m1;
            }
            for (int j0 = w0 + 32; j0 < i; j0 += 4) {
                float4 f0 = *(const float4*)(cf0 + j0);
                float4 f1 = *(const float4*)(cf1v + j0);
                float4 f2 = *(const float4*)(cf2v + j0);
                float4 f3 = *(const float4*)(cf3v + j0);
                float m0 = M[(j0 + 0) * 129 + t];
                float m1 = M[(j0 + 1) * 129 + t];
                float m2 = M[(j0 + 2) * 129 + t];
                float m3 = M[(j0 + 3) * 129 + t];
                p0 -= f0.x * m0 + f0.y * m1 + f0.z * m2 + f0.w * m3;
                p1 -= f1.x * m0 + f1.y * m1 + f1.z * m2 + f1.w * m3;
                p2 -= f2.x * m0 + f2.y * m1 + f2.z * m2 + f2.w * m3;
                p3 -= f3.x * m0 + f3.y * m1 + f3.z * m2 + f3.w * m3;
            }
            a0 = p0; a1 = p1; a2 = p2; a3 = p3;
        } else {
            // straddle warp: per-lane masks; include_k = (t >= i+k) || (j > t)
            a0 = (t >= i)     ? gg0 : -c0;
            a1 = (t >= i + 1) ? gg1 : ((t >= i) ? 0.f : -c1);
            a2 = (t >= i + 2) ? gg2 : ((t >= i) ? 0.f : -c2);
            a3 = (t >= i + 3) ? gg3 : ((t >= i) ? 0.f : -c3);
            for (int j = 0; j < i; j++) {
                float m = M[j * 129 + t];
                bool jt = (j > t);
                a0 -= (((t >= i)     || jt) ? cf0[j]  : 0.f) * m;
                a1 -= (((t >= i + 1) || jt) ? cf1v[j] : 0.f) * m;
                a2 -= (((t >= i + 2) || jt) ? cf2v[j] : 0.f) * m;
                a3 -= (((t >= i + 3) || jt) ? cf3v[j] : 0.f) * m;
            }
        }

        // completion step 0: row i final
        if (t == i)     { invnn = 1.f / a0; pub[0] = invnn; }
        if (t == i + 1) pub[3] = a0;
        if (t == i + 2) pub[4] = a0;
        if (t == i + 3) pub[5] = a0;
        __syncthreads();
        // step 1: row i+1
        {
            float cf = pub[3] * pub[0];
            float m0 = (t == i) ? 1.f : a0;
            a1 -= cf * m0;
        }
        if (t == i + 1) { invnn = 1.f / a1; pub[1] = invnn; }
        if (t == i + 2) pub[6] = a1;
        if (t == i + 3) pub[7] = a1;
        __syncthreads();
        // step 2: row i+2
        {
            float cf20 = pub[4] * pub[0];
            float cf21 = pub[6] * pub[1];
            float m0 = (t == i) ? 1.f : ((t == i + 1) ? 0.f : a0);
            float m1 = (t == i + 1) ? 1.f : a1;
            a2 -= cf20 * m0 + cf21 * m1;
        }
        if (t == i + 2) { invnn = 1.f / a2; pub[2] = invnn; }
        if (t == i + 3) pub[8] = a2;
        __syncthreads();
        // step 3: row i+3
        {
            float cf30 = pub[5] * pub[0];
            float cf31 = pub[7] * pub[1];
            float cf32 = pub[8] * pub[2];
            float m0 = (t == i) ? 1.f : ((t == i + 1 || t == i + 2) ? 0.f : a0);
            float m1 = (t == i + 1) ? 1.f : ((t == i + 2) ? 0.f : a1);
            float m2 = (t == i + 2) ? 1.f : a2;
            a3 -= cf30 * m0 + cf31 * m1 + cf32 * m2;
        }
        if (t == i + 3) invnn = 1.f / a3;

        M[(i + 0) * 129 + t] = a0;
        M[(i + 1) * 129 + t] = a1;
        M[(i + 2) * 129 + t] = a2;
        M[(i + 3) * 129 + t] = a3;
        __syncthreads();
    }

    // writeback L: unit diag, zeros above
    float* Lb = g_L + (size_t)bc * (NV * NV);
#pragma unroll 4
    for (int r = 0; r < NV; r++) {
        float v = (t < r) ? M[r * 129 + t] : ((t == r) ? 1.f : 0.f);
        Lb[r * NV + t] = v;
    }
}

// ---------------------------------------------------------------- kernel C
// Q = L @ Xchunk via HMMA bf16 hi/lo (3 terms). (R11 version — known good.)
#define LT 18432                // 128 * 144 B  (L tile, 64 k)
#define XT 17408                // 64 * 272 B   (X tile, 128 d)
__global__ void __launch_bounds__(256) gs_apply_mma(const float* __restrict__ X,
                                                   float* __restrict__ out) {
    extern __shared__ __align__(16) char smc[];
    const int bc = blockIdx.x >> 3;
    const int dc = blockIdx.x & 7;
    const int t = threadIdx.x, lane = t & 31, wid = t >> 5;
    const int wp = wid >> 2;
    const int wn = (wid & 3) * 32;
    const uint32_t sb = smem_u32(smc);
    const uint32_t Lh = sb, Ll = sb + LT, Xh = sb + 2 * LT, Xl = sb + 2 * LT + XT;

    const float* Xb = X + (size_t)bc * (NV * DD) + dc * 128;
    const float* Lb = g_L + (size_t)bc * (NV * NV);

    float acc[4][4][4];
#pragma unroll
    for (int mt = 0; mt < 4; mt++)
#pragma unroll
        for (int nt = 0; nt < 4; nt++)
#pragma unroll
            for (int r = 0; r < 4; r++) acc[mt][nt][r] = 0.f;

    const uint32_t lane_a = (uint32_t)((lane >> 2) * 144 + (lane & 3) * 4);
    const int brow = (lane & 7) + (lane & 8);
    const int bcol = wn + ((lane >> 4) << 3);

    for (int ch = 0; ch < 2; ch++) {
#pragma unroll
        for (int it = 0; it < 8; it++) {
            int fl = t + 256 * it;
            int r = fl >> 4, c4 = fl & 15;
            float4 v = *(const float4*)(Lb + r * NV + ch * 64 + c4 * 4);
            uint32_t h01, h23, l01, l23;
            bf16_split4(v, h01, h23, l01, l23);
            uint32_t off = (uint32_t)(r * 144 + c4 * 8);
            asm volatile("st.shared.v2.b32 [%0], {%1,%2};"
                         :: "r"(Lh + off), "r"(h01), "r"(h23) : "memory");
            asm volatile("st.shared.v2.b32 [%0], {%1,%2};"
                         :: "r"(Ll + off), "r"(l01), "r"(l23) : "memory");
        }
#pragma unroll
        for (int it = 0; it < 8; it++) {
            int fl = t + 256 * it;
            int r = fl >> 5, c4 = fl & 31;
            float4 v = *(const float4*)(Xb + (ch * 64 + r) * DD + c4 * 4);
            uint32_t h01, h23, l01, l23;
            bf16_split4(v, h01, h23, l01, l23);
            uint32_t off = (uint32_t)(r * 272 + c4 * 8);
            asm volatile("st.shared.v2.b32 [%0], {%1,%2};"
                         :: "r"(Xh + off), "r"(h01), "r"(h23) : "memory");
            asm volatile("st.shared.v2.b32 [%0], {%1,%2};"
                         :: "r"(Xl + off), "r"(l01), "r"(l23) : "memory");
        }
        __syncthreads();

#pragma unroll
        for (int ks = 0; ks < 4; ks++) {
            const int kg = ch * 4 + ks;
            uint32_t Bh[4][2], Bl[4][2];
#pragma unroll
            for (int nb2 = 0; nb2 < 2; nb2++) {
                uint32_t ba = (uint32_t)((ks * 16 + brow) * 272 + (bcol + nb2 * 16) * 2);
                uint32_t r0, r1, r2, r3;
                asm volatile("ldmatrix.sync.aligned.m8n8.x4.trans.shared.b16 "
                             "{%0,%1,%2,%3}, [%4];"
                             : "=r"(r0), "=r"(r1), "=r"(r2), "=r"(r3) : "r"(Xh + ba));
                Bh[nb2 * 2][0] = r0; Bh[nb2 * 2][1] = r1;
                Bh[nb2 * 2 + 1][0] = r2; Bh[nb2 * 2 + 1][1] = r3;
                asm volatile("ldmatrix.sync.aligned.m8n8.x4.trans.shared.b16 "
                             "{%0,%1,%2,%3}, [%4];"
                             : "=r"(r0), "=r"(r1), "=r"(r2), "=r"(r3) : "r"(Xl + ba));
                Bl[nb2 * 2][0] = r0; Bl[nb2 * 2][1] = r1;
                Bl[nb2 * 2 + 1][0] = r2; Bl[nb2 * 2 + 1][1] = r3;
            }
#pragma unroll
            for (int mt = 0; mt < 4; mt++) {
                if (kg <= 2 * mt + wp) {
                    uint32_t ah = Lh + (uint32_t)((2 * mt + wp) * 2304 + ks * 32) + lane_a;
                    uint32_t al = Ll + (uint32_t)((2 * mt + wp) * 2304 + ks * 32) + lane_a;
                    uint32_t A0, A1, A2, A3, a0, a1, a2, a3;
                    asm volatile("ld.shared.b32 %0, [%1];"      : "=r"(A0) : "r"(ah));
                    asm volatile("ld.shared.b32 %0, [%1+1152];" : "=r"(A1) : "r"(ah));
                    asm volatile("ld.shared.b32 %0, [%1+16];"   : "=r"(A2) : "r"(ah));
                    asm volatile("ld.shared.b32 %0, [%1+1168];" : "=r"(A3) : "r"(ah));
                    asm volatile("ld.shared.b32 %0, [%1];"      : "=r"(a0) : "r"(al));
                    asm volatile("ld.shared.b32 %0, [%1+1152];" : "=r"(a1) : "r"(al));
                    asm volatile("ld.shared.b32 %0, [%1+16];"   : "=r"(a2) : "r"(al));
                    asm volatile("ld.shared.b32 %0, [%1+1168];" : "=r"(a3) : "r"(al));
#pragma unroll
                    for (int nt = 0; nt < 4; nt++) {
                        mma_bf16(acc[mt][nt], A0, A1, A2, A3, Bh[nt][0], Bh[nt][1]);
                        mma_bf16(acc[mt][nt], A0, A1, A2, A3, Bl[nt][0], Bl[nt][1]);
                        mma_bf16(acc[mt][nt], a0, a1, a2, a3, Bh[nt][0], Bh[nt][1]);
                    }
                }
            }
        }
        __syncthreads();
    }

    float* Qs = (float*)smc;                 // 128 x 132 fp32
    float* rn = Qs + 128 * 132;
#pragma unroll
    for (int mt = 0; mt < 4; mt++) {
        int row = (2 * mt + wp) * 16 + (lane >> 2);
#pragma unroll
        for (int nt = 0; nt < 4; nt++) {
            int col = wn + nt * 8 + (lane & 3) * 2;
            *(float2*)(Qs + row * 132 + col)       = make_float2(acc[mt][nt][0], acc[mt][nt][1]);
            *(float2*)(Qs + (row + 8) * 132 + col) = make_float2(acc[mt][nt][2], acc[mt][nt][3]);
        }
    }
    __syncthreads();

    if (t < 128) {
        float s = 0.f;
#pragma unroll 4
        for (int i = 0; i < 128; i++) { float q = Qs[i * 132 + t]; s += q * q; }
        rn[t] = rsqrtf(s);
    }
    __syncthreads();

    float* ob = out + (size_t)bc * (NV * DD) + dc * 128;
#pragma unroll
    for (int it = 0; it < 16; it++) {
        int fl = t + 256 * it;
        int r = fl >> 5, c4 = fl & 31;
        float4 q = *(float4*)(Qs + r * 132 + c4 * 4);
        q.x *= rn[c4 * 4 + 0];
        q.y *= rn[c4 * 4 + 1];
        q.z *= rn[c4 * 4 + 2];
        q.w *= rn[c4 * 4 + 3];
        *(float4*)(ob + r * DD + c4 * 4) = q;
    }
}

// ---------------------------------------------------------------- launcher
extern "C" void kernel_launch(void* const* d_in, const int* in_sizes, int n_in,
                              void* d_out, int out_size) {
    const float* x = (const float*)d_in[0];
    float* out = (float*)d_out;

    const int smA = 4 * TILE_B;                                         // 73728
    const int smB = (NV * 129 + 4 * NV + 16) * (int)sizeof(float);      // 68160
    const int smC = 2 * LT + 2 * XT;                                    // 71680

    cudaFuncSetAttribute(gs_gram_mma,    cudaFuncAttributeMaxDynamicSharedMemorySize, smA);
    cudaFuncSetAttribute(gs_chol_kernel, cudaFuncAttributeMaxDynamicSharedMemorySize, smB);
    cudaFuncSetAttribute(gs_apply_mma,   cudaFuncAttributeMaxDynamicSharedMemorySize, smC);

    gs_gram_mma<<<NBC, 256, smA>>>(x);
    gs_chol_kernel<<<NBC, 128, smB>>>();
    gs_apply_mma<<<NBC * 8, 256, smC>>>(x, out);
}

// round 14
// speedup vs baseline: 1.1454x; 1.0082x over previous
#include <cuda_runtime.h>
#include <cuda_bf16.h>
#include <stdint.h>
#include <math.h>

// GramSchmidt: x[8,32,128,1024] fp32.
// G = X X^T per (b,c) via mma.sync bf16 (hi/lo split, 3 terms, fp32 acc);
// 4-column blocked triangular-overlay recurrence (fully vectorized straddle);
// Q = L X via mma.sync bf16; out = Q * rsqrt(colsumsq_over_N(Q)).

#define NBC 256
#define NV  128
#define DD  1024

__device__ float g_G[NBC * NV * NV];
__device__ float g_L[NBC * NV * NV];

__device__ __forceinline__ uint32_t smem_u32(const void* p) {
    uint32_t a;
    asm("{ .reg .u64 t; cvta.to.shared.u64 t, %1; cvt.u32.u64 %0, t; }"
        : "=r"(a) : "l"(p));
    return a;
}

__device__ __forceinline__ void mma_bf16(float* d, uint32_t a0, uint32_t a1,
                                         uint32_t a2, uint32_t a3,
                                         uint32_t b0, uint32_t b1) {
    asm volatile(
        "mma.sync.aligned.m16n8k16.row.col.f32.bf16.bf16.f32 "
        "{%0,%1,%2,%3}, {%4,%5,%6,%7}, {%8,%9}, {%0,%1,%2,%3};"
        : "+f"(d[0]), "+f"(d[1]), "+f"(d[2]), "+f"(d[3])
        : "r"(a0), "r"(a1), "r"(a2), "r"(a3), "r"(b0), "r"(b1));
}

__device__ __forceinline__ void bf16_split4(float4 v, uint32_t& h01, uint32_t& h23,
                                            uint32_t& l01, uint32_t& l23) {
    __nv_bfloat16 hx = __float2bfloat16(v.x), hy = __float2bfloat16(v.y);
    __nv_bfloat16 hz = __float2bfloat16(v.z), hw = __float2bfloat16(v.w);
    __nv_bfloat16 lx = __float2bfloat16(v.x - __bfloat162float(hx));
    __nv_bfloat16 ly = __float2bfloat16(v.y - __bfloat162float(hy));
    __nv_bfloat16 lz = __float2bfloat16(v.z - __bfloat162float(hz));
    __nv_bfloat16 lw = __float2bfloat16(v.w - __bfloat162float(hw));
    h01 = ((uint32_t)__bfloat16_as_ushort(hy) << 16) | __bfloat16_as_ushort(hx);
    h23 = ((uint32_t)__bfloat16_as_ushort(hw) << 16) | __bfloat16_as_ushort(hz);
    l01 = ((uint32_t)__bfloat16_as_ushort(ly) << 16) | __bfloat16_as_ushort(lx);
    l23 = ((uint32_t)__bfloat16_as_ushort(lw) << 16) | __bfloat16_as_ushort(lz);
}

// ---------------------------------------------------------------- kernel A
// G[bc] = X X^T via HMMA bf16 hi/lo split, 3 terms. Pipelined, 1 BAR/chunk.
#define TILE_B 18432            // 128 * 144 bytes
__global__ void __launch_bounds__(256) gs_gram_mma(const float* __restrict__ X) {
    extern __shared__ __align__(16) char smc[];
    const int bc = blockIdx.x;
    const float* Xb = X + (size_t)bc * (NV * DD);
    const int t = threadIdx.x, lane = t & 31, wid = t >> 5;
    const int wm = (wid >> 2) * 64;
    const int wn = (wid & 3) * 32;
    const uint32_t sb = smem_u32(smc);

    float acc[4][4][4];
#pragma unroll
    for (int mt = 0; mt < 4; mt++)
#pragma unroll
        for (int nt = 0; nt < 4; nt++)
#pragma unroll
            for (int r = 0; r < 4; r++) acc[mt][nt][r] = 0.f;

    const uint32_t lane_a = (uint32_t)((lane >> 2) * 144 + (lane & 3) * 4);

    float4 pf[8];
#pragma unroll
    for (int it = 0; it < 8; it++) {
        int fl = t + 256 * it;
        pf[it] = *(const float4*)(Xb + (fl >> 4) * DD + (fl & 15) * 4);
    }
#pragma unroll
    for (int it = 0; it < 8; it++) {
        int fl = t + 256 * it;
        int r = fl >> 4, c4 = fl & 15;
        uint32_t h01, h23, l01, l23;
        bf16_split4(pf[it], h01, h23, l01, l23);
        uint32_t off = (uint32_t)(r * 144 + c4 * 8);
        asm volatile("st.shared.v2.b32 [%0], {%1,%2};"
                     :: "r"(sb + off), "r"(h01), "r"(h23) : "memory");
        asm volatile("st.shared.v2.b32 [%0], {%1,%2};"
                     :: "r"(sb + TILE_B + off), "r"(l01), "r"(l23) : "memory");
    }
    __syncthreads();

    for (int ch = 0; ch < 16; ch++) {
        const uint32_t hi_s = sb + (uint32_t)(ch & 1) * (2 * TILE_B);
        const uint32_t lo_s = hi_s + TILE_B;
        if (ch + 1 < 16) {
#pragma unroll
            for (int it = 0; it < 8; it++) {
                int fl = t + 256 * it;
                pf[it] = *(const float4*)(Xb + (fl >> 4) * DD + (ch + 1) * 64 + (fl & 15) * 4);
            }
        }

#pragma unroll
        for (int ks = 0; ks < 4; ks++) {
            const uint32_t kb = (uint32_t)(ks * 32);
            uint32_t Ah[4][4], Al[4][4], Bh[4][2], Bl[4][2];
#pragma unroll
            for (int mt = 0; mt < 4; mt++) {
                uint32_t ah = hi_s + (uint32_t)((wm + mt * 16) * 144) + kb + lane_a;
                uint32_t al = lo_s + (uint32_t)((wm + mt * 16) * 144) + kb + lane_a;
                asm volatile("ld.shared.b32 %0, [%1];"       : "=r"(Ah[mt][0]) : "r"(ah));
                asm volatile("ld.shared.b32 %0, [%1+1152];"  : "=r"(Ah[mt][1]) : "r"(ah));
                asm volatile("ld.shared.b32 %0, [%1+16];"    : "=r"(Ah[mt][2]) : "r"(ah));
                asm volatile("ld.shared.b32 %0, [%1+1168];"  : "=r"(Ah[mt][3]) : "r"(ah));
                asm volatile("ld.shared.b32 %0, [%1];"       : "=r"(Al[mt][0]) : "r"(al));
                asm volatile("ld.shared.b32 %0, [%1+1152];"  : "=r"(Al[mt][1]) : "r"(al));
                asm volatile("ld.shared.b32 %0, [%1+16];"    : "=r"(Al[mt][2]) : "r"(al));
                asm volatile("ld.shared.b32 %0, [%1+1168];"  : "=r"(Al[mt][3]) : "r"(al));
            }
#pragma unroll
            for (int nt = 0; nt < 4; nt++) {
                uint32_t bh = hi_s + (uint32_t)((wn + nt * 8) * 144) + kb + lane_a;
                uint32_t bl = lo_s + (uint32_t)((wn + nt * 8) * 144) + kb + lane_a;
                asm volatile("ld.shared.b32 %0, [%1];"    : "=r"(Bh[nt][0]) : "r"(bh));
                asm volatile("ld.shared.b32 %0, [%1+16];" : "=r"(Bh[nt][1]) : "r"(bh));
                asm volatile("ld.shared.b32 %0, [%1];"    : "=r"(Bl[nt][0]) : "r"(bl));
                asm volatile("ld.shared.b32 %0, [%1+16];" : "=r"(Bl[nt][1]) : "r"(bl));
            }
#pragma unroll
            for (int mt = 0; mt < 4; mt++)
#pragma unroll
                for (int nt = 0; nt < 4; nt++) {
                    mma_bf16(acc[mt][nt], Ah[mt][0], Ah[mt][1], Ah[mt][2], Ah[mt][3],
                             Bh[nt][0], Bh[nt][1]);
                    mma_bf16(acc[mt][nt], Ah[mt][0], Ah[mt][1], Ah[mt][2], Ah[mt][3],
                             Bl[nt][0], Bl[nt][1]);
                    mma_bf16(acc[mt][nt], Al[mt][0], Al[mt][1], Al[mt][2], Al[mt][3],
                             Bh[nt][0], Bh[nt][1]);
                }
        }

        if (ch + 1 < 16) {
            const uint32_t nhi = sb + (uint32_t)((ch + 1) & 1) * (2 * TILE_B);
            const uint32_t nlo = nhi + TILE_B;
#pragma unroll
            for (int it = 0; it < 8; it++) {
                int fl = t + 256 * it;
                int r = fl >> 4, c4 = fl & 15;
                uint32_t h01, h23, l01, l23;
                bf16_split4(pf[it], h01, h23, l01, l23);
                uint32_t off = (uint32_t)(r * 144 + c4 * 8);
                asm volatile("st.shared.v2.b32 [%0], {%1,%2};"
                             :: "r"(nhi + off), "r"(h01), "r"(h23) : "memory");
                asm volatile("st.shared.v2.b32 [%0], {%1,%2};"
                             :: "r"(nlo + off), "r"(l01), "r"(l23) : "memory");
            }
        }
        __syncthreads();
    }

    float* Gb = g_G + (size_t)bc * (NV * NV);
#pragma unroll
    for (int mt = 0; mt < 4; mt++) {
        int row = wm + mt * 16 + (lane >> 2);
#pragma unroll
        for (int nt = 0; nt < 4; nt++) {
            int col = wn + nt * 8 + (lane & 3) * 2;
            *(float2*)(Gb + row * NV + col)       = make_float2(acc[mt][nt][0], acc[mt][nt][1]);
            *(float2*)(Gb + (row + 8) * NV + col) = make_float2(acc[mt][nt][2], acc[mt][nt][3]);
        }
    }
}

// ---------------------------------------------------------------- kernel B
// 4-column blocked triangular-overlay recurrence; straddle warp vectorized:
//   S_k = sum_{j<w0} cf_k[j] M[j][t]              (unmasked float4 chunks)
//   T_k = sum_{j in [w0,w0+32)} mask_k cf_k[j] M[j][t],
//         mask_k = (t >= i+k) || (j > t)          (overshoot terms exact 0)
//   a_k = base_k - (t >= i+k ? S_k : 0) - T_k
__global__ void gs_chol_kernel() {
    extern __shared__ float M[];                // 128 x 129
    float* cf0 = M + NV * 129;
    float* cf1v = cf0 + NV;
    float* cf2v = cf1v + NV;
    float* cf3v = cf2v + NV;
    float* pub = cf3v + NV;                     // 16

    const int bc = blockIdx.x;
    const int t  = threadIdx.x;
    const int w0 = t & ~31;
    const float* Gb = g_G + (size_t)bc * (NV * NV);

#pragma unroll
    for (int it = 0; it < 129; it++) M[it * 128 + t] = 0.f;
    cf0[t] = 0.f; cf1v[t] = 0.f; cf2v[t] = 0.f; cf3v[t] = 0.f;
    __syncthreads();

    float invnn = 1.f;
    float g0 = Gb[t];
    M[t] = g0;
    if (t == 0) invnn = 1.f / g0;
    __syncthreads();
    {   // row 1
        float g1 = Gb[NV + t];
        if (t == 0) pub[0] = M[1] * invnn;
        __syncthreads();
        float cf = pub[0];
        float v = (t >= 1) ? (g1 - cf * M[t]) : -cf;
        M[129 + t] = v;
        if (t == 1) invnn = 1.f / v;
        __syncthreads();
    }
    {   // pair i=2 (rows 2,3): tiny scalar body
        const int i = 2;
        float g1 = Gb[i * NV + t];
        float g2 = Gb[(i + 1) * NV + t];
        float c1 = (t < i) ? M[t * 129 + i] * invnn : 0.f;
        float c2 = (t < i) ? M[t * 129 + i + 1] * invnn : 0.f;
        cf0[t] = c1; cf1v[t] = c2;
        __syncthreads();

        float a1 = (t >= i) ? g1 : -c1;
        float a2 = (t > i)  ? g2 : ((t == i) ? 0.f : -c2);
        for (int j = 0; j < i; j++) {
            float m = M[j * 129 + t];
            float f1 = ((t >= i) || (j > t)) ? cf0[j] : 0.f;
            float f2 = ((t > i)  || (j > t)) ? cf1v[j] : 0.f;
            a1 -= f1 * m;
            a2 -= f2 * m;
        }
        M[i * 129 + t] = a1;
        if (t == i)     { invnn = 1.f / a1; pub[0] = invnn; }
        if (t == i + 1) { pub[1] = a1; }
        __syncthreads();
        float cf2i = pub[1] * pub[0];
        a2 -= cf2i * ((t == i) ? 1.f : a1);
        M[(i + 1) * 129 + t] = a2;
        if (t == i + 1) invnn = 1.f / a2;
        __syncthreads();
    }

    // 4-blocks i = 4, 8, ..., 124
    for (int i = 4; i < NV; i += 4) {
        float gg0 = Gb[(i + 0) * NV + t];
        float gg1 = Gb[(i + 1) * NV + t];
        float gg2 = Gb[(i + 2) * NV + t];
        float gg3 = Gb[(i + 3) * NV + t];

        float c0 = 0.f, c1 = 0.f, c2 = 0.f, c3 = 0.f;
        if (t < i) {
            const float* Mr = M + t * 129 + i;
            c0 = Mr[0] * invnn; c1 = Mr[1] * invnn;
            c2 = Mr[2] * invnn; c3 = Mr[3] * invnn;
        }
        cf0[t] = c0; cf1v[t] = c1; cf2v[t] = c2; cf3v[t] = c3;
        __syncthreads();

        float a0, a1, a2, a3;
        if (w0 > i + 3) {
            // pure P: all t >= i+4
            float p0 = gg0, p1 = gg1, p2 = gg2, p3 = gg3;
            for (int j0 = 0; j0 < i; j0 += 4) {
                float4 f0 = *(const float4*)(cf0 + j0);
                float4 f1 = *(const float4*)(cf1v + j0);
                float4 f2 = *(const float4*)(cf2v + j0);
                float4 f3 = *(const float4*)(cf3v + j0);
                float m0 = M[(j0 + 0) * 129 + t];
                float m1 = M[(j0 + 1) * 129 + t];
                float m2 = M[(j0 + 2) * 129 + t];
                float m3 = M[(j0 + 3) * 129 + t];
                p0 -= f0.x * m0 + f0.y * m1 + f0.z * m2 + f0.w * m3;
                p1 -= f1.x * m0 + f1.y * m1 + f1.z * m2 + f1.w * m3;
                p2 -= f2.x * m0 + f2.y * m1 + f2.z * m2 + f2.w * m3;
                p3 -= f3.x * m0 + f3.y * m1 + f3.z * m2 + f3.w * m3;
            }
            a0 = p0; a1 = p1; a2 = p2; a3 = p3;
        } else if (w0 + 32 <= i) {
            // pure L: all t < i
            float p0 = -c0, p1 = -c1, p2 = -c2, p3 = -c3;
#pragma unroll
            for (int j = 0; j < 32; j += 2) {
                int jj = w0 + j;
                float m0 = M[(jj + 0) * 129 + t];
                float m1 = M[(jj + 1) * 129 + t];
                bool s0 = (jj + 0 > t), s1 = (jj + 1 > t);
                p0 -= (s0 ? cf0[jj] : 0.f) * m0 + (s1 ? cf0[jj + 1] : 0.f) * m1;
                p1 -= (s0 ? cf1v[jj] : 0.f) * m0 + (s1 ? cf1v[jj + 1] : 0.f) * m1;
                p2 -= (s0 ? cf2v[jj] : 0.f) * m0 + (s1 ? cf2v[jj + 1] : 0.f) * m1;
                p3 -= (s0 ? cf3v[jj] : 0.f) * m0 + (s1 ? cf3v[jj + 1] : 0.f) * m1;
            }
            for (int j0 = w0 + 32; j0 < i; j0 += 4) {
                float4 f0 = *(const float4*)(cf0 + j0);
                float4 f1 = *(const float4*)(cf1v + j0);
                float4 f2 = *(const float4*)(cf2v + j0);
                float4 f3 = *(const float4*)(cf3v + j0);
                float m0 = M[(j0 + 0) * 129 + t];
                float m1 = M[(j0 + 1) * 129 + t];
                float m2 = M[(j0 + 2) * 129 + t];
                float m3 = M[(j0 + 3) * 129 + t];
                p0 -= f0.x * m0 + f0.y * m1 + f0.z * m2 + f0.w * m3;
                p1 -= f1.x * m0 + f1.y * m1 + f1.z * m2 + f1.w * m3;
                p2 -= f2.x * m0 + f2.y * m1 + f2.z * m2 + f2.w * m3;
                p3 -= f3.x * m0 + f3.y * m1 + f3.z * m2 + f3.w * m3;
            }
            a0 = p0; a1 = p1; a2 = p2; a3 = p3;
        } else {
            // straddle warp, vectorized:
            // full chunks j < w0 (apply to lanes t >= i+k only)
            float S0 = 0.f, S1 = 0.f, S2 = 0.f, S3 = 0.f;
            for (int j0 = 0; j0 < w0; j0 += 4) {
                float4 f0 = *(const float4*)(cf0 + j0);
                float4 f1 = *(const float4*)(cf1v + j0);
                float4 f2 = *(const float4*)(cf2v + j0);
                float4 f3 = *(const float4*)(cf3v + j0);
                float m0 = M[(j0 + 0) * 129 + t];
                float m1 = M[(j0 + 1) * 129 + t];
                float m2 = M[(j0 + 2) * 129 + t];
                float m3 = M[(j0 + 3) * 129 + t];
                S0 += f0.x * m0 + f0.y * m1 + f0.z * m2 + f0.w * m3;
                S1 += f1.x * m0 + f1.y * m1 + f1.z * m2 + f1.w * m3;
                S2 += f2.x * m0 + f2.y * m1 + f2.z * m2 + f2.w * m3;
                S3 += f3.x * m0 + f3.y * m1 + f3.z * m2 + f3.w * m3;
            }
            // masked chunk [w0, w0+32): overshoot (j >= i) terms are exact 0
            float T0 = 0.f, T1 = 0.f, T2 = 0.f, T3 = 0.f;
#pragma unroll
            for (int j = 0; j < 32; j += 2) {
                int jj = w0 + j;
                float m0 = M[(jj + 0) * 129 + t];
                float m1 = M[(jj + 1) * 129 + t];
                bool j0t = (jj + 0 > t), j1t = (jj + 1 > t);
                T0 += (((t >= i)     || j0t) ? cf0[jj]      : 0.f) * m0
                    + (((t >= i)     || j1t) ? cf0[jj + 1]  : 0.f) * m1;
                T1 += (((t >= i + 1) || j0t) ? cf1v[jj]     : 0.f) * m0
                    + (((t >= i + 1) || j1t) ? cf1v[jj + 1] : 0.f) * m1;
                T2 += (((t >= i + 2) || j0t) ? cf2v[jj]     : 0.f) * m0
                    + (((t >= i + 2) || j1t) ? cf2v[jj + 1] : 0.f) * m1;
                T3 += (((t >= i + 3) || j0t) ? cf3v[jj]     : 0.f) * m0
                    + (((t >= i + 3) || j1t) ? cf3v[jj + 1] : 0.f) * m1;
            }
            float b0 = (t >= i)     ? gg0 : -c0;
            float b1 = (t >= i + 1) ? gg1 : ((t >= i) ? 0.f : -c1);
            float b2 = (t >= i + 2) ? gg2 : ((t >= i) ? 0.f : -c2);
            float b3 = (t >= i + 3) ? gg3 : ((t >= i) ? 0.f : -c3);
            a0 = b0 - ((t >= i)     ? S0 : 0.f) - T0;
            a1 = b1 - ((t >= i + 1) ? S1 : 0.f) - T1;
            a2 = b2 - ((t >= i + 2) ? S2 : 0.f) - T2;
            a3 = b3 - ((t >= i + 3) ? S3 : 0.f) - T3;
        }

        // completion step 0: row i final
        if (t == i)     { invnn = 1.f / a0; pub[0] = invnn; }
        if (t == i + 1) pub[3] = a0;
        if (t == i + 2) pub[4] = a0;
        if (t == i + 3) pub[5] = a0;
        __syncthreads();
        // step 1: row i+1
        {
            float cf = pub[3] * pub[0];
            float m0 = (t == i) ? 1.f : a0;
            a1 -= cf * m0;
        }
        if (t == i + 1) { invnn = 1.f / a1; pub[1] = invnn; }
        if (t == i + 2) pub[6] = a1;
        if (t == i + 3) pub[7] = a1;
        __syncthreads();
        // step 2: row i+2
        {
            float cf20 = pub[4] * pub[0];
            float cf21 = pub[6] * pub[1];
            float m0 = (t == i) ? 1.f : ((t == i + 1) ? 0.f : a0);
            float m1 = (t == i + 1) ? 1.f : a1;
            a2 -= cf20 * m0 + cf21 * m1;
        }
        if (t == i + 2) { invnn = 1.f / a2; pub[2] = invnn; }
        if (t == i + 3) pub[8] = a2;
        __syncthreads();
        // step 3: row i+3
        {
            float cf30 = pub[5] * pub[0];
            float cf31 = pub[7] * pub[1];
            float cf32 = pub[8] * pub[2];
            float m0 = (t == i) ? 1.f : ((t == i + 1 || t == i + 2) ? 0.f : a0);
            float m1 = (t == i + 1) ? 1.f : ((t == i + 2) ? 0.f : a1);
            float m2 = (t == i + 2) ? 1.f : a2;
            a3 -= cf30 * m0 + cf31 * m1 + cf32 * m2;
        }
        if (t == i + 3) invnn = 1.f / a3;

        M[(i + 0) * 129 + t] = a0;
        M[(i + 1) * 129 + t] = a1;
        M[(i + 2) * 129 + t] = a2;
        M[(i + 3) * 129 + t] = a3;
        __syncthreads();
    }

    float* Lb = g_L + (size_t)bc * (NV * NV);
#pragma unroll 4
    for (int r = 0; r < NV; r++) {
        float v = (t < r) ? M[r * 129 + t] : ((t == r) ? 1.f : 0.f);
        Lb[r * NV + t] = v;
    }
}

// ---------------------------------------------------------------- kernel C
// Q = L @ Xchunk via HMMA bf16 hi/lo (3 terms). (R11 version — known good.)
#define LT 18432                // 128 * 144 B  (L tile, 64 k)
#define XT 17408                // 64 * 272 B   (X tile, 128 d)
__global__ void __launch_bounds__(256) gs_apply_mma(const float* __restrict__ X,
                                                   float* __restrict__ out) {
    extern __shared__ __align__(16) char smc[];
    const int bc = blockIdx.x >> 3;
    const int dc = blockIdx.x & 7;
    const int t = threadIdx.x, lane = t & 31, wid = t >> 5;
    const int wp = wid >> 2;
    const int wn = (wid & 3) * 32;
    const uint32_t sb = smem_u32(smc);
    const uint32_t Lh = sb, Ll = sb + LT, Xh = sb + 2 * LT, Xl = sb + 2 * LT + XT;

    const float* Xb = X + (size_t)bc * (NV * DD) + dc * 128;
    const float* Lb = g_L + (size_t)bc * (NV * NV);

    float acc[4][4][4];
#pragma unroll
    for (int mt = 0; mt < 4; mt++)
#pragma unroll
        for (int nt = 0; nt < 4; nt++)
#pragma unroll
            for (int r = 0; r < 4; r++) acc[mt][nt][r] = 0.f;

    const uint32_t lane_a = (uint32_t)((lane >> 2) * 144 + (lane & 3) * 4);
    const int brow = (lane & 7) + (lane & 8);
    const int bcol = wn + ((lane >> 4) << 3);

    for (int ch = 0; ch < 2; ch++) {
#pragma unroll
        for (int it = 0; it < 8; it++) {
            int fl = t + 256 * it;
            int r = fl >> 4, c4 = fl & 15;
            float4 v = *(const float4*)(Lb + r * NV + ch * 64 + c4 * 4);
            uint32_t h01, h23, l01, l23;
            bf16_split4(v, h01, h23, l01, l23);
            uint32_t off = (uint32_t)(r * 144 + c4 * 8);
            asm volatile("st.shared.v2.b32 [%0], {%1,%2};"
                         :: "r"(Lh + off), "r"(h01), "r"(h23) : "memory");
            asm volatile("st.shared.v2.b32 [%0], {%1,%2};"
                         :: "r"(Ll + off), "r"(l01), "r"(l23) : "memory");
        }
#pragma unroll
        for (int it = 0; it < 8; it++) {
            int fl = t + 256 * it;
            int r = fl >> 5, c4 = fl & 31;
            float4 v = *(const float4*)(Xb + (ch * 64 + r) * DD + c4 * 4);
            uint32_t h01, h23, l01, l23;
            bf16_split4(v, h01, h23, l01, l23);
            uint32_t off = (uint32_t)(r * 272 + c4 * 8);
            asm volatile("st.shared.v2.b32 [%0], {%1,%2};"
                         :: "r"(Xh + off), "r"(h01), "r"(h23) : "memory");
            asm volatile("st.shared.v2.b32 [%0], {%1,%2};"
                         :: "r"(Xl + off), "r"(l01), "r"(l23) : "memory");
        }
        __syncthreads();

#pragma unroll
        for (int ks = 0; ks < 4; ks++) {
            const int kg = ch * 4 + ks;
            uint32_t Bh[4][2], Bl[4][2];
#pragma unroll
            for (int nb2 = 0; nb2 < 2; nb2++) {
                uint32_t ba = (uint32_t)((ks * 16 + brow) * 272 + (bcol + nb2 * 16) * 2);
                uint32_t r0, r1, r2, r3;
                asm volatile("ldmatrix.sync.aligned.m8n8.x4.trans.shared.b16 "
                             "{%0,%1,%2,%3}, [%4];"
                             : "=r"(r0), "=r"(r1), "=r"(r2), "=r"(r3) : "r"(Xh + ba));
                Bh[nb2 * 2][0] = r0; Bh[nb2 * 2][1] = r1;
                Bh[nb2 * 2 + 1][0] = r2; Bh[nb2 * 2 + 1][1] = r3;
                asm volatile("ldmatrix.sync.aligned.m8n8.x4.trans.shared.b16 "
                             "{%0,%1,%2,%3}, [%4];"
                             : "=r"(r0), "=r"(r1), "=r"(r2), "=r"(r3) : "r"(Xl + ba));
                Bl[nb2 * 2][0] = r0; Bl[nb2 * 2][1] = r1;
                Bl[nb2 * 2 + 1][0] = r2; Bl[nb2 * 2 + 1][1] = r3;
            }
#pragma unroll
            for (int mt = 0; mt < 4; mt++) {
                if (kg <= 2 * mt + wp) {
                    uint32_t ah = Lh + (uint32_t)((2 * mt + wp) * 2304 + ks * 32) + lane_a;
                    uint32_t al = Ll + (uint32_t)((2 * mt + wp) * 2304 + ks * 32) + lane_a;
                    uint32_t A0, A1, A2, A3, a0, a1, a2, a3;
                    asm volatile("ld.shared.b32 %0, [%1];"      : "=r"(A0) : "r"(ah));
                    asm volatile("ld.shared.b32 %0, [%1+1152];" : "=r"(A1) : "r"(ah));
                    asm volatile("ld.shared.b32 %0, [%1+16];"   : "=r"(A2) : "r"(ah));
                    asm volatile("ld.shared.b32 %0, [%1+1168];" : "=r"(A3) : "r"(ah));
                    asm volatile("ld.shared.b32 %0, [%1];"      : "=r"(a0) : "r"(al));
                    asm volatile("ld.shared.b32 %0, [%1+1152];" : "=r"(a1) : "r"(al));
                    asm volatile("ld.shared.b32 %0, [%1+16];"   : "=r"(a2) : "r"(al));
                    asm volatile("ld.shared.b32 %0, [%1+1168];" : "=r"(a3) : "r"(al));
#pragma unroll
                    for (int nt = 0; nt < 4; nt++) {
                        mma_bf16(acc[mt][nt], A0, A1, A2, A3, Bh[nt][0], Bh[nt][1]);
                        mma_bf16(acc[mt][nt], A0, A1, A2, A3, Bl[nt][0], Bl[nt][1]);
                        mma_bf16(acc[mt][nt], a0, a1, a2, a3, Bh[nt][0], Bh[nt][1]);
                    }
                }
            }
        }
        __syncthreads();
    }

    float* Qs = (float*)smc;                 // 128 x 132 fp32
    float* rn = Qs + 128 * 132;
#pragma unroll
    for (int mt = 0; mt < 4; mt++) {
        int row = (2 * mt + wp) * 16 + (lane >> 2);
#pragma unroll
        for (int nt = 0; nt < 4; nt++) {
            int col = wn + nt * 8 + (lane & 3) * 2;
            *(float2*)(Qs + row * 132 + col)       = make_float2(acc[mt][nt][0], acc[mt][nt][1]);
            *(float2*)(Qs + (row + 8) * 132 + col) = make_float2(acc[mt][nt][2], acc[mt][nt][3]);
        }
    }
    __syncthreads();

    if (t < 128) {
        float s = 0.f;
#pragma unroll 4
        for (int i = 0; i < 128; i++) { float q = Qs[i * 132 + t]; s += q * q; }
        rn[t] = rsqrtf(s);
    }
    __syncthreads();

    float* ob = out + (size_t)bc * (NV * DD) + dc * 128;
#pragma unroll
    for (int it = 0; it < 16; it++) {
        int fl = t + 256 * it;
        int r = fl >> 5, c4 = fl & 31;
        float4 q = *(float4*)(Qs + r * 132 + c4 * 4);
        q.x *= rn[c4 * 4 + 0];
        q.y *= rn[c4 * 4 + 1];
        q.z *= rn[c4 * 4 + 2];
        q.w *= rn[c4 * 4 + 3];
        *(float4*)(ob + r * DD + c4 * 4) = q;
    }
}

// ---------------------------------------------------------------- launcher
extern "C" void kernel_launch(void* const* d_in, const int* in_sizes, int n_in,
                              void* d_out, int out_size) {
    const float* x = (const float*)d_in[0];
    float* out = (float*)d_out;

    const int smA = 4 * TILE_B;                                         // 73728
    const int smB = (NV * 129 + 4 * NV + 16) * (int)sizeof(float);      // 68160
    const int smC = 2 * LT + 2 * XT;                                    // 71680

    cudaFuncSetAttribute(gs_gram_mma,    cudaFuncAttributeMaxDynamicSharedMemorySize, smA);
    cudaFuncSetAttribute(gs_chol_kernel, cudaFuncAttributeMaxDynamicSharedMemorySize, smB);
    cudaFuncSetAttribute(gs_apply_mma,   cudaFuncAttributeMaxDynamicSharedMemorySize, smC);

    gs_gram_mma<<<NBC, 256, smA>>>(x);
    gs_chol_kernel<<<NBC, 128, smB>>>();
    gs_apply_mma<<<NBC * 8, 256, smC>>>(x, out);
}

// round 15
// speedup vs baseline: 1.1839x; 1.0336x over previous
#include <cuda_runtime.h>
#include <cuda_bf16.h>
#include <stdint.h>
#include <math.h>

// GramSchmidt: x[8,32,128,1024] fp32.
// G = X X^T per (b,c) via mma.sync bf16 (hi/lo split, 3 terms, fp32 acc),
// SYMMETRIC tile skip (upper-triangle tiles only + mirrored writeback);
// 4-column blocked triangular-overlay recurrence; Q = L X via mma.sync bf16;
// out = Q * rsqrt(colsumsq_over_N(Q)).

#define NBC 256
#define NV  128
#define DD  1024

__device__ float g_G[NBC * NV * NV];
__device__ float g_L[NBC * NV * NV];

__device__ __forceinline__ uint32_t smem_u32(const void* p) {
    uint32_t a;
    asm("{ .reg .u64 t; cvta.to.shared.u64 t, %1; cvt.u32.u64 %0, t; }"
        : "=r"(a) : "l"(p));
    return a;
}

__device__ __forceinline__ void mma_bf16(float* d, uint32_t a0, uint32_t a1,
                                         uint32_t a2, uint32_t a3,
                                         uint32_t b0, uint32_t b1) {
    asm volatile(
        "mma.sync.aligned.m16n8k16.row.col.f32.bf16.bf16.f32 "
        "{%0,%1,%2,%3}, {%4,%5,%6,%7}, {%8,%9}, {%0,%1,%2,%3};"
        : "+f"(d[0]), "+f"(d[1]), "+f"(d[2]), "+f"(d[3])
        : "r"(a0), "r"(a1), "r"(a2), "r"(a3), "r"(b0), "r"(b1));
}

__device__ __forceinline__ void bf16_split4(float4 v, uint32_t& h01, uint32_t& h23,
                                            uint32_t& l01, uint32_t& l23) {
    __nv_bfloat16 hx = __float2bfloat16(v.x), hy = __float2bfloat16(v.y);
    __nv_bfloat16 hz = __float2bfloat16(v.z), hw = __float2bfloat16(v.w);
    __nv_bfloat16 lx = __float2bfloat16(v.x - __bfloat162float(hx));
    __nv_bfloat16 ly = __float2bfloat16(v.y - __bfloat162float(hy));
    __nv_bfloat16 lz = __float2bfloat16(v.z - __bfloat162float(hz));
    __nv_bfloat16 lw = __float2bfloat16(v.w - __bfloat162float(hw));
    h01 = ((uint32_t)__bfloat16_as_ushort(hy) << 16) | __bfloat16_as_ushort(hx);
    h23 = ((uint32_t)__bfloat16_as_ushort(hw) << 16) | __bfloat16_as_ushort(hz);
    l01 = ((uint32_t)__bfloat16_as_ushort(ly) << 16) | __bfloat16_as_ushort(lx);
    l23 = ((uint32_t)__bfloat16_as_ushort(lw) << 16) | __bfloat16_as_ushort(lz);
}

// ---------------------------------------------------------------- kernel A
// G[bc] = X X^T via HMMA bf16 hi/lo split, 3 terms. Pipelined, 1 BAR/chunk.
// Symmetric skip: m0 = 16(2mt+wp), n0 = 32nt+8wq; compute tile iff n0 >= m0.
// Writeback: direct iff c >= r, mirror G[c][r] iff c > r (each element once).
#define TILE_B 18432            // 128 * 144 bytes
__global__ void __launch_bounds__(256) gs_gram_mma(const float* __restrict__ X) {
    extern __shared__ __align__(16) char smc[];
    const int bc = blockIdx.x;
    const float* Xb = X + (size_t)bc * (NV * DD);
    const int t = threadIdx.x, lane = t & 31, wid = t >> 5;
    const int wp = wid >> 2;               // 0..1  (m interleave)
    const int wq = wid & 3;                // 0..3  (n interleave)
    const uint32_t sb = smem_u32(smc);

    float acc[4][4][4];
#pragma unroll
    for (int mt = 0; mt < 4; mt++)
#pragma unroll
        for (int nt = 0; nt < 4; nt++)
#pragma unroll
            for (int r = 0; r < 4; r++) acc[mt][nt][r] = 0.f;

    const uint32_t lane_a = (uint32_t)((lane >> 2) * 144 + (lane & 3) * 4);

    float4 pf[8];
#pragma unroll
    for (int it = 0; it < 8; it++) {
        int fl = t + 256 * it;
        pf[it] = *(const float4*)(Xb + (fl >> 4) * DD + (fl & 15) * 4);
    }
#pragma unroll
    for (int it = 0; it < 8; it++) {
        int fl = t + 256 * it;
        int r = fl >> 4, c4 = fl & 15;
        uint32_t h01, h23, l01, l23;
        bf16_split4(pf[it], h01, h23, l01, l23);
        uint32_t off = (uint32_t)(r * 144 + c4 * 8);
        asm volatile("st.shared.v2.b32 [%0], {%1,%2};"
                     :: "r"(sb + off), "r"(h01), "r"(h23) : "memory");
        asm volatile("st.shared.v2.b32 [%0], {%1,%2};"
                     :: "r"(sb + TILE_B + off), "r"(l01), "r"(l23) : "memory");
    }
    __syncthreads();

    for (int ch = 0; ch < 16; ch++) {
        const uint32_t hi_s = sb + (uint32_t)(ch & 1) * (2 * TILE_B);
        const uint32_t lo_s = hi_s + TILE_B;
        if (ch + 1 < 16) {
#pragma unroll
            for (int it = 0; it < 8; it++) {
                int fl = t + 256 * it;
                pf[it] = *(const float4*)(Xb + (fl >> 4) * DD + (ch + 1) * 64 + (fl & 15) * 4);
            }
        }

#pragma unroll
        for (int ks = 0; ks < 4; ks++) {
            const uint32_t kb = (uint32_t)(ks * 32);
            uint32_t Ah[4][4], Al[4][4], Bh[4][2], Bl[4][2];
#pragma unroll
            for (int mt = 0; mt < 4; mt++) {
                if (96 + 8 * wq >= 32 * mt + 16 * wp) {   // any nt kept for this mt
                    int m0 = 16 * (2 * mt + wp);
                    uint32_t ah = hi_s + (uint32_t)(m0 * 144) + kb + lane_a;
                    uint32_t al = lo_s + (uint32_t)(m0 * 144) + kb + lane_a;
                    asm volatile("ld.shared.b32 %0, [%1];"       : "=r"(Ah[mt][0]) : "r"(ah));
                    asm volatile("ld.shared.b32 %0, [%1+1152];"  : "=r"(Ah[mt][1]) : "r"(ah));
                    asm volatile("ld.shared.b32 %0, [%1+16];"    : "=r"(Ah[mt][2]) : "r"(ah));
                    asm volatile("ld.shared.b32 %0, [%1+1168];"  : "=r"(Ah[mt][3]) : "r"(ah));
                    asm volatile("ld.shared.b32 %0, [%1];"       : "=r"(Al[mt][0]) : "r"(al));
                    asm volatile("ld.shared.b32 %0, [%1+1152];"  : "=r"(Al[mt][1]) : "r"(al));
                    asm volatile("ld.shared.b32 %0, [%1+16];"    : "=r"(Al[mt][2]) : "r"(al));
                    asm volatile("ld.shared.b32 %0, [%1+1168];"  : "=r"(Al[mt][3]) : "r"(al));
                }
            }
#pragma unroll
            for (int nt = 0; nt < 4; nt++) {
                if (32 * nt + 8 * wq >= 16 * wp) {        // any mt kept for this nt
                    int n0 = 32 * nt + 8 * wq;
                    uint32_t bh = hi_s + (uint32_t)(n0 * 144) + kb + lane_a;
                    uint32_t bl = lo_s + (uint32_t)(n0 * 144) + kb + lane_a;
                    asm volatile("ld.shared.b32 %0, [%1];"    : "=r"(Bh[nt][0]) : "r"(bh));
                    asm volatile("ld.shared.b32 %0, [%1+16];" : "=r"(Bh[nt][1]) : "r"(bh));
                    asm volatile("ld.shared.b32 %0, [%1];"    : "=r"(Bl[nt][0]) : "r"(bl));
                    asm volatile("ld.shared.b32 %0, [%1+16];" : "=r"(Bl[nt][1]) : "r"(bl));
                }
            }
#pragma unroll
            for (int mt = 0; mt < 4; mt++)
#pragma unroll
                for (int nt = 0; nt < 4; nt++) {
                    if (32 * nt + 8 * wq >= 32 * mt + 16 * wp) {   // keep tile
                        mma_bf16(acc[mt][nt], Ah[mt][0], Ah[mt][1], Ah[mt][2], Ah[mt][3],
                                 Bh[nt][0], Bh[nt][1]);
                        mma_bf16(acc[mt][nt], Ah[mt][0], Ah[mt][1], Ah[mt][2], Ah[mt][3],
                                 Bl[nt][0], Bl[nt][1]);
                        mma_bf16(acc[mt][nt], Al[mt][0], Al[mt][1], Al[mt][2], Al[mt][3],
                                 Bh[nt][0], Bh[nt][1]);
                    }
                }
        }

        if (ch + 1 < 16) {
            const uint32_t nhi = sb + (uint32_t)((ch + 1) & 1) * (2 * TILE_B);
            const uint32_t nlo = nhi + TILE_B;
#pragma unroll
            for (int it = 0; it < 8; it++) {
                int fl = t + 256 * it;
                int r = fl >> 4, c4 = fl & 15;
                uint32_t h01, h23, l01, l23;
                bf16_split4(pf[it], h01, h23, l01, l23);
                uint32_t off = (uint32_t)(r * 144 + c4 * 8);
                asm volatile("st.shared.v2.b32 [%0], {%1,%2};"
                             :: "r"(nhi + off), "r"(h01), "r"(h23) : "memory");
                asm volatile("st.shared.v2.b32 [%0], {%1,%2};"
                             :: "r"(nlo + off), "r"(l01), "r"(l23) : "memory");
            }
        }
        __syncthreads();
    }

    // writeback: each element exactly once (direct upper+diag, mirror lower)
    float* Gb = g_G + (size_t)bc * (NV * NV);
#pragma unroll
    for (int mt = 0; mt < 4; mt++)
#pragma unroll
        for (int nt = 0; nt < 4; nt++) {
            if (32 * nt + 8 * wq >= 32 * mt + 16 * wp) {
                int row = 16 * (2 * mt + wp) + (lane >> 2);
                int col = 32 * nt + 8 * wq + (lane & 3) * 2;
#pragma unroll
                for (int e = 0; e < 4; e++) {
                    int r = row + (e >> 1) * 8;
                    int c = col + (e & 1);
                    float v = acc[mt][nt][e];
                    if (c >= r) Gb[r * NV + c] = v;
                    if (c > r)  Gb[c * NV + r] = v;
                }
            }
        }
}

// ---------------------------------------------------------------- kernel B
// 4-column blocked triangular-overlay recurrence (R14 version).
__global__ void gs_chol_kernel() {
    extern __shared__ float M[];                // 128 x 129
    float* cf0 = M + NV * 129;
    float* cf1v = cf0 + NV;
    float* cf2v = cf1v + NV;
    float* cf3v = cf2v + NV;
    float* pub = cf3v + NV;                     // 16

    const int bc = blockIdx.x;
    const int t  = threadIdx.x;
    const int w0 = t & ~31;
    const float* Gb = g_G + (size_t)bc * (NV * NV);

#pragma unroll
    for (int it = 0; it < 129; it++) M[it * 128 + t] = 0.f;
    cf0[t] = 0.f; cf1v[t] = 0.f; cf2v[t] = 0.f; cf3v[t] = 0.f;
    __syncthreads();

    float invnn = 1.f;
    float g0 = Gb[t];
    M[t] = g0;
    if (t == 0) invnn = 1.f / g0;
    __syncthreads();
    {   // row 1
        float g1 = Gb[NV + t];
        if (t == 0) pub[0] = M[1] * invnn;
        __syncthreads();
        float cf = pub[0];
        float v = (t >= 1) ? (g1 - cf * M[t]) : -cf;
        M[129 + t] = v;
        if (t == 1) invnn = 1.f / v;
        __syncthreads();
    }
    {   // pair i=2 (rows 2,3)
        const int i = 2;
        float g1 = Gb[i * NV + t];
        float g2 = Gb[(i + 1) * NV + t];
        float c1 = (t < i) ? M[t * 129 + i] * invnn : 0.f;
        float c2 = (t < i) ? M[t * 129 + i + 1] * invnn : 0.f;
        cf0[t] = c1; cf1v[t] = c2;
        __syncthreads();

        float a1 = (t >= i) ? g1 : -c1;
        float a2 = (t > i)  ? g2 : ((t == i) ? 0.f : -c2);
        for (int j = 0; j < i; j++) {
            float m = M[j * 129 + t];
            float f1 = ((t >= i) || (j > t)) ? cf0[j] : 0.f;
            float f2 = ((t > i)  || (j > t)) ? cf1v[j] : 0.f;
            a1 -= f1 * m;
            a2 -= f2 * m;
        }
        M[i * 129 + t] = a1;
        if (t == i)     { invnn = 1.f / a1; pub[0] = invnn; }
        if (t == i + 1) { pub[1] = a1; }
        __syncthreads();
        float cf2i = pub[1] * pub[0];
        a2 -= cf2i * ((t == i) ? 1.f : a1);
        M[(i + 1) * 129 + t] = a2;
        if (t == i + 1) invnn = 1.f / a2;
        __syncthreads();
    }

    for (int i = 4; i < NV; i += 4) {
        float gg0 = Gb[(i + 0) * NV + t];
        float gg1 = Gb[(i + 1) * NV + t];
        float gg2 = Gb[(i + 2) * NV + t];
        float gg3 = Gb[(i + 3) * NV + t];

        float c0 = 0.f, c1 = 0.f, c2 = 0.f, c3 = 0.f;
        if (t < i) {
            const float* Mr = M + t * 129 + i;
            c0 = Mr[0] * invnn; c1 = Mr[1] * invnn;
            c2 = Mr[2] * invnn; c3 = Mr[3] * invnn;
        }
        cf0[t] = c0; cf1v[t] = c1; cf2v[t] = c2; cf3v[t] = c3;
        __syncthreads();

        float a0, a1, a2, a3;
        if (w0 > i + 3) {
            float p0 = gg0, p1 = gg1, p2 = gg2, p3 = gg3;
            for (int j0 = 0; j0 < i; j0 += 4) {
                float4 f0 = *(const float4*)(cf0 + j0);
                float4 f1 = *(const float4*)(cf1v + j0);
                float4 f2 = *(const float4*)(cf2v + j0);
                float4 f3 = *(const float4*)(cf3v + j0);
                float m0 = M[(j0 + 0) * 129 + t];
                float m1 = M[(j0 + 1) * 129 + t];
                float m2 = M[(j0 + 2) * 129 + t];
                float m3 = M[(j0 + 3) * 129 + t];
                p0 -= f0.x * m0 + f0.y * m1 + f0.z * m2 + f0.w * m3;
                p1 -= f1.x * m0 + f1.y * m1 + f1.z * m2 + f1.w * m3;
                p2 -= f2.x * m0 + f2.y * m1 + f2.z * m2 + f2.w * m3;
                p3 -= f3.x * m0 + f3.y * m1 + f3.z * m2 + f3.w * m3;
            }
            a0 = p0; a1 = p1; a2 = p2; a3 = p3;
        } else if (w0 + 32 <= i) {
            float p0 = -c0, p1 = -c1, p2 = -c2, p3 = -c3;
#pragma unroll
            for (int j = 0; j < 32; j += 2) {
                int jj = w0 + j;
                float m0 = M[(jj + 0) * 129 + t];
                float m1 = M[(jj + 1) * 129 + t];
                bool s0 = (jj + 0 > t), s1 = (jj + 1 > t);
                p0 -= (s0 ? cf0[jj] : 0.f) * m0 + (s1 ? cf0[jj + 1] : 0.f) * m1;
                p1 -= (s0 ? cf1v[jj] : 0.f) * m0 + (s1 ? cf1v[jj + 1] : 0.f) * m1;
                p2 -= (s0 ? cf2v[jj] : 0.f) * m0 + (s1 ? cf2v[jj + 1] : 0.f) * m1;
                p3 -= (s0 ? cf3v[jj] : 0.f) * m0 + (s1 ? cf3v[jj + 1] : 0.f) * m1;
            }
            for (int j0 = w0 + 32; j0 < i; j0 += 4) {
                float4 f0 = *(const float4*)(cf0 + j0);
                float4 f1 = *(const float4*)(cf1v + j0);
                float4 f2 = *(const float4*)(cf2v + j0);
                float4 f3 = *(const float4*)(cf3v + j0);
                float m0 = M[(j0 + 0) * 129 + t];
                float m1 = M[(j0 + 1) * 129 + t];
                float m2 = M[(j0 + 2) * 129 + t];
                float m3 = M[(j0 + 3) * 129 + t];
                p0 -= f0.x * m0 + f0.y * m1 + f0.z * m2 + f0.w * m3;
                p1 -= f1.x * m0 + f1.y * m1 + f1.z * m2 + f1.w * m3;
                p2 -= f2.x * m0 + f2.y * m1 + f2.z * m2 + f2.w * m3;
                p3 -= f3.x * m0 + f3.y * m1 + f3.z * m2 + f3.w * m3;
            }
            a0 = p0; a1 = p1; a2 = p2; a3 = p3;
        } else {
            float S0 = 0.f, S1 = 0.f, S2 = 0.f, S3 = 0.f;
            for (int j0 = 0; j0 < w0; j0 += 4) {
                float4 f0 = *(const float4*)(cf0 + j0);
                float4 f1 = *(const float4*)(cf1v + j0);
                float4 f2 = *(const float4*)(cf2v + j0);
                float4 f3 = *(const float4*)(cf3v + j0);
                float m0 = M[(j0 + 0) * 129 + t];
                float m1 = M[(j0 + 1) * 129 + t];
                float m2 = M[(j0 + 2) * 129 + t];
                float m3 = M[(j0 + 3) * 129 + t];
                S0 += f0.x * m0 + f0.y * m1 + f0.z * m2 + f0.w * m3;
                S1 += f1.x * m0 + f1.y * m1 + f1.z * m2 + f1.w * m3;
                S2 += f2.x * m0 + f2.y * m1 + f2.z * m2 + f2.w * m3;
                S3 += f3.x * m0 + f3.y * m1 + f3.z * m2 + f3.w * m3;
            }
            float T0 = 0.f, T1 = 0.f, T2 = 0.f, T3 = 0.f;
#pragma unroll
            for (int j = 0; j < 32; j += 2) {
                int jj = w0 + j;
                float m0 = M[(jj + 0) * 129 + t];
                float m1 = M[(jj + 1) * 129 + t];
                bool j0t = (jj + 0 > t), j1t = (jj + 1 > t);
                T0 += (((t >= i)     || j0t) ? cf0[jj]      : 0.f) * m0
                    + (((t >= i)     || j1t) ? cf0[jj + 1]  : 0.f) * m1;
                T1 += (((t >= i + 1) || j0t) ? cf1v[jj]     : 0.f) * m0
                    + (((t >= i + 1) || j1t) ? cf1v[jj + 1] : 0.f) * m1;
                T2 += (((t >= i + 2) || j0t) ? cf2v[jj]     : 0.f) * m0
                    + (((t >= i + 2) || j1t) ? cf2v[jj + 1] : 0.f) * m1;
                T3 += (((t >= i + 3) || j0t) ? cf3v[jj]     : 0.f) * m0
                    + (((t >= i + 3) || j1t) ? cf3v[jj + 1] : 0.f) * m1;
            }
            float b0 = (t >= i)     ? gg0 : -c0;
            float b1 = (t >= i + 1) ? gg1 : ((t >= i) ? 0.f : -c1);
            float b2 = (t >= i + 2) ? gg2 : ((t >= i) ? 0.f : -c2);
            float b3 = (t >= i + 3) ? gg3 : ((t >= i) ? 0.f : -c3);
            a0 = b0 - ((t >= i)     ? S0 : 0.f) - T0;
            a1 = b1 - ((t >= i + 1) ? S1 : 0.f) - T1;
            a2 = b2 - ((t >= i + 2) ? S2 : 0.f) - T2;
            a3 = b3 - ((t >= i + 3) ? S3 : 0.f) - T3;
        }

        if (t == i)     { invnn = 1.f / a0; pub[0] = invnn; }
        if (t == i + 1) pub[3] = a0;
        if (t == i + 2) pub[4] = a0;
        if (t == i + 3) pub[5] = a0;
        __syncthreads();
        {
            float cf = pub[3] * pub[0];
            float m0 = (t == i) ? 1.f : a0;
            a1 -= cf * m0;
        }
        if (t == i + 1) { invnn = 1.f / a1; pub[1] = invnn; }
        if (t == i + 2) pub[6] = a1;
        if (t == i + 3) pub[7] = a1;
        __syncthreads();
        {
            float cf20 = pub[4] * pub[0];
            float cf21 = pub[6] * pub[1];
            float m0 = (t == i) ? 1.f : ((t == i + 1) ? 0.f : a0);
            float m1 = (t == i + 1) ? 1.f : a1;
            a2 -= cf20 * m0 + cf21 * m1;
        }
        if (t == i + 2) { invnn = 1.f / a2; pub[2] = invnn; }
        if (t == i + 3) pub[8] = a2;
        __syncthreads();
        {
            float cf30 = pub[5] * pub[0];
            float cf31 = pub[7] * pub[1];
            float cf32 = pub[8] * pub[2];
            float m0 = (t == i) ? 1.f : ((t == i + 1 || t == i + 2) ? 0.f : a0);
            float m1 = (t == i + 1) ? 1.f : ((t == i + 2) ? 0.f : a1);
            float m2 = (t == i + 2) ? 1.f : a2;
            a3 -= cf30 * m0 + cf31 * m1 + cf32 * m2;
        }
        if (t == i + 3) invnn = 1.f / a3;

        M[(i + 0) * 129 + t] = a0;
        M[(i + 1) * 129 + t] = a1;
        M[(i + 2) * 129 + t] = a2;
        M[(i + 3) * 129 + t] = a3;
        __syncthreads();
    }

    float* Lb = g_L + (size_t)bc * (NV * NV);
#pragma unroll 4
    for (int r = 0; r < NV; r++) {
        float v = (t < r) ? M[r * 129 + t] : ((t == r) ? 1.f : 0.f);
        Lb[r * NV + t] = v;
    }
}

// ---------------------------------------------------------------- kernel C
// Q = L @ Xchunk via HMMA bf16 hi/lo (3 terms). (R11 version — known good.)
#define LT 18432                // 128 * 144 B  (L tile, 64 k)
#define XT 17408                // 64 * 272 B   (X tile, 128 d)
__global__ void __launch_bounds__(256) gs_apply_mma(const float* __restrict__ X,
                                                   float* __restrict__ out) {
    extern __shared__ __align__(16) char smc[];
    const int bc = blockIdx.x >> 3;
    const int dc = blockIdx.x & 7;
    const int t = threadIdx.x, lane = t & 31, wid = t >> 5;
    const int wp = wid >> 2;
    const int wn = (wid & 3) * 32;
    const uint32_t sb = smem_u32(smc);
    const uint32_t Lh = sb, Ll = sb + LT, Xh = sb + 2 * LT, Xl = sb + 2 * LT + XT;

    const float* Xb = X + (size_t)bc * (NV * DD) + dc * 128;
    const float* Lb = g_L + (size_t)bc * (NV * NV);

    float acc[4][4][4];
#pragma unroll
    for (int mt = 0; mt < 4; mt++)
#pragma unroll
        for (int nt = 0; nt < 4; nt++)
#pragma unroll
            for (int r = 0; r < 4; r++) acc[mt][nt][r] = 0.f;

    const uint32_t lane_a = (uint32_t)((lane >> 2) * 144 + (lane & 3) * 4);
    const int brow = (lane & 7) + (lane & 8);
    const int bcol = wn + ((lane >> 4) << 3);

    for (int ch = 0; ch < 2; ch++) {
#pragma unroll
        for (int it = 0; it < 8; it++) {
            int fl = t + 256 * it;
            int r = fl >> 4, c4 = fl & 15;
            float4 v = *(const float4*)(Lb + r * NV + ch * 64 + c4 * 4);
            uint32_t h01, h23, l01, l23;
            bf16_split4(v, h01, h23, l01, l23);
            uint32_t off = (uint32_t)(r * 144 + c4 * 8);
            asm volatile("st.shared.v2.b32 [%0], {%1,%2};"
                         :: "r"(Lh + off), "r"(h01), "r"(h23) : "memory");
            asm volatile("st.shared.v2.b32 [%0], {%1,%2};"
                         :: "r"(Ll + off), "r"(l01), "r"(l23) : "memory");
        }
#pragma unroll
        for (int it = 0; it < 8; it++) {
            int fl = t + 256 * it;
            int r = fl >> 5, c4 = fl & 31;
            float4 v = *(const float4*)(Xb + (ch * 64 + r) * DD + c4 * 4);
            uint32_t h01, h23, l01, l23;
            bf16_split4(v, h01, h23, l01, l23);
            uint32_t off = (uint32_t)(r * 272 + c4 * 8);
            asm volatile("st.shared.v2.b32 [%0], {%1,%2};"
                         :: "r"(Xh + off), "r"(h01), "r"(h23) : "memory");
            asm volatile("st.shared.v2.b32 [%0], {%1,%2};"
                         :: "r"(Xl + off), "r"(l01), "r"(l23) : "memory");
        }
        __syncthreads();

#pragma unroll
        for (int ks = 0; ks < 4; ks++) {
            const int kg = ch * 4 + ks;
            uint32_t Bh[4][2], Bl[4][2];
#pragma unroll
            for (int nb2 = 0; nb2 < 2; nb2++) {
                uint32_t ba = (uint32_t)((ks * 16 + brow) * 272 + (bcol + nb2 * 16) * 2);
                uint32_t r0, r1, r2, r3;
                asm volatile("ldmatrix.sync.aligned.m8n8.x4.trans.shared.b16 "
                             "{%0,%1,%2,%3}, [%4];"
                             : "=r"(r0), "=r"(r1), "=r"(r2), "=r"(r3) : "r"(Xh + ba));
                Bh[nb2 * 2][0] = r0; Bh[nb2 * 2][1] = r1;
                Bh[nb2 * 2 + 1][0] = r2; Bh[nb2 * 2 + 1][1] = r3;
                asm volatile("ldmatrix.sync.aligned.m8n8.x4.trans.shared.b16 "
                             "{%0,%1,%2,%3}, [%4];"
                             : "=r"(r0), "=r"(r1), "=r"(r2), "=r"(r3) : "r"(Xl + ba));
                Bl[nb2 * 2][0] = r0; Bl[nb2 * 2][1] = r1;
                Bl[nb2 * 2 + 1][0] = r2; Bl[nb2 * 2 + 1][1] = r3;
            }
#pragma unroll
            for (int mt = 0; mt < 4; mt++) {
                if (kg <= 2 * mt + wp) {
                    uint32_t ah = Lh + (uint32_t)((2 * mt + wp) * 2304 + ks * 32) + lane_a;
                    uint32_t al = Ll + (uint32_t)((2 * mt + wp) * 2304 + ks * 32) + lane_a;
                    uint32_t A0, A1, A2, A3, a0, a1, a2, a3;
                    asm volatile("ld.shared.b32 %0, [%1];"      : "=r"(A0) : "r"(ah));
                    asm volatile("ld.shared.b32 %0, [%1+1152];" : "=r"(A1) : "r"(ah));
                    asm volatile("ld.shared.b32 %0, [%1+16];"   : "=r"(A2) : "r"(ah));
                    asm volatile("ld.shared.b32 %0, [%1+1168];" : "=r"(A3) : "r"(ah));
                    asm volatile("ld.shared.b32 %0, [%1];"      : "=r"(a0) : "r"(al));
                    asm volatile("ld.shared.b32 %0, [%1+1152];" : "=r"(a1) : "r"(al));
                    asm volatile("ld.shared.b32 %0, [%1+16];"   : "=r"(a2) : "r"(al));
                    asm volatile("ld.shared.b32 %0, [%1+1168];" : "=r"(a3) : "r"(al));
#pragma unroll
                    for (int nt = 0; nt < 4; nt++) {
                        mma_bf16(acc[mt][nt], A0, A1, A2, A3, Bh[nt][0], Bh[nt][1]);
                        mma_bf16(acc[mt][nt], A0, A1, A2, A3, Bl[nt][0], Bl[nt][1]);
                        mma_bf16(acc[mt][nt], a0, a1, a2, a3, Bh[nt][0], Bh[nt][1]);
                    }
                }
            }
        }
        __syncthreads();
    }

    float* Qs = (float*)smc;                 // 128 x 132 fp32
    float* rn = Qs + 128 * 132;
#pragma unroll
    for (int mt = 0; mt < 4; mt++) {
        int row = (2 * mt + wp) * 16 + (lane >> 2);
#pragma unroll
        for (int nt = 0; nt < 4; nt++) {
            int col = wn + nt * 8 + (lane & 3) * 2;
            *(float2*)(Qs + row * 132 + col)       = make_float2(acc[mt][nt][0], acc[mt][nt][1]);
            *(float2*)(Qs + (row + 8) * 132 + col) = make_float2(acc[mt][nt][2], acc[mt][nt][3]);
        }
    }
    __syncthreads();

    if (t < 128) {
        float s = 0.f;
#pragma unroll 4
        for (int i = 0; i < 128; i++) { float q = Qs[i * 132 + t]; s += q * q; }
        rn[t] = rsqrtf(s);
    }
    __syncthreads();

    float* ob = out + (size_t)bc * (NV * DD) + dc * 128;
#pragma unroll
    for (int it = 0; it < 16; it++) {
        int fl = t + 256 * it;
        int r = fl >> 5, c4 = fl & 31;
        float4 q = *(float4*)(Qs + r * 132 + c4 * 4);
        q.x *= rn[c4 * 4 + 0];
        q.y *= rn[c4 * 4 + 1];
        q.z *= rn[c4 * 4 + 2];
        q.w *= rn[c4 * 4 + 3];
        *(float4*)(ob + r * DD + c4 * 4) = q;
    }
}

// ---------------------------------------------------------------- launcher
extern "C" void kernel_launch(void* const* d_in, const int* in_sizes, int n_in,
                              void* d_out, int out_size) {
    const float* x = (const float*)d_in[0];
    float* out = (float*)d_out;

    const int smA = 4 * TILE_B;                                         // 73728
    const int smB = (NV * 129 + 4 * NV + 16) * (int)sizeof(float);      // 68160
    const int smC = 2 * LT + 2 * XT;                                    // 71680

    cudaFuncSetAttribute(gs_gram_mma,    cudaFuncAttributeMaxDynamicSharedMemorySize, smA);
    cudaFuncSetAttribute(gs_chol_kernel, cudaFuncAttributeMaxDynamicSharedMemorySize, smB);
    cudaFuncSetAttribute(gs_apply_mma,   cudaFuncAttributeMaxDynamicSharedMemorySize, smC);

    gs_gram_mma<<<NBC, 256, smA>>>(x);
    gs_chol_kernel<<<NBC, 128, smB>>>();
    gs_apply_mma<<<NBC * 8, 256, smC>>>(x, out);
}

// round 17
// speedup vs baseline: 1.2197x; 1.0302x over previous
#include <cuda_runtime.h>
#include <cuda_bf16.h>
#include <stdint.h>
#include <math.h>

// GramSchmidt: x[8,32,128,1024] fp32.
// G = X X^T per (b,c) via mma.sync bf16 (hi/lo, 3 terms) + symmetric skip;
// BLOCKED (16-row panel) triangular-overlay recurrence: per-panel GEMM for
// cross-panel corrections + tiny within-panel recurrence;
// Q = L X via mma.sync bf16; out = Q * rsqrt(colsumsq_over_N(Q)).

#define NBC 256
#define NV  128
#define DD  1024
#define CFS 20     // cfA row stride in floats (80 B, float4-aligned)

__device__ float g_G[NBC * NV * NV];
__device__ float g_L[NBC * NV * NV];

__device__ __forceinline__ uint32_t smem_u32(const void* p) {
    uint32_t a;
    asm("{ .reg .u64 t; cvta.to.shared.u64 t, %1; cvt.u32.u64 %0, t; }"
        : "=r"(a) : "l"(p));
    return a;
}

__device__ __forceinline__ void mma_bf16(float* d, uint32_t a0, uint32_t a1,
                                         uint32_t a2, uint32_t a3,
                                         uint32_t b0, uint32_t b1) {
    asm volatile(
        "mma.sync.aligned.m16n8k16.row.col.f32.bf16.bf16.f32 "
        "{%0,%1,%2,%3}, {%4,%5,%6,%7}, {%8,%9}, {%0,%1,%2,%3};"
        : "+f"(d[0]), "+f"(d[1]), "+f"(d[2]), "+f"(d[3])
        : "r"(a0), "r"(a1), "r"(a2), "r"(a3), "r"(b0), "r"(b1));
}

__device__ __forceinline__ void bf16_split4(float4 v, uint32_t& h01, uint32_t& h23,
                                            uint32_t& l01, uint32_t& l23) {
    __nv_bfloat16 hx = __float2bfloat16(v.x), hy = __float2bfloat16(v.y);
    __nv_bfloat16 hz = __float2bfloat16(v.z), hw = __float2bfloat16(v.w);
    __nv_bfloat16 lx = __float2bfloat16(v.x - __bfloat162float(hx));
    __nv_bfloat16 ly = __float2bfloat16(v.y - __bfloat162float(hy));
    __nv_bfloat16 lz = __float2bfloat16(v.z - __bfloat162float(hz));
    __nv_bfloat16 lw = __float2bfloat16(v.w - __bfloat162float(hw));
    h01 = ((uint32_t)__bfloat16_as_ushort(hy) << 16) | __bfloat16_as_ushort(hx);
    h23 = ((uint32_t)__bfloat16_as_ushort(hw) << 16) | __bfloat16_as_ushort(hz);
    l01 = ((uint32_t)__bfloat16_as_ushort(ly) << 16) | __bfloat16_as_ushort(lx);
    l23 = ((uint32_t)__bfloat16_as_ushort(lw) << 16) | __bfloat16_as_ushort(lz);
}

// ---------------------------------------------------------------- kernel A
// (R15 version: symmetric skip + mirrored writeback)
#define TILE_B 18432
__global__ void __launch_bounds__(256) gs_gram_mma(const float* __restrict__ X) {
    extern __shared__ __align__(16) char smc[];
    const int bc = blockIdx.x;
    const float* Xb = X + (size_t)bc * (NV * DD);
    const int t = threadIdx.x, lane = t & 31, wid = t >> 5;
    const int wp = wid >> 2;
    const int wq = wid & 3;
    const uint32_t sb = smem_u32(smc);

    float acc[4][4][4];
#pragma unroll
    for (int mt = 0; mt < 4; mt++)
#pragma unroll
        for (int nt = 0; nt < 4; nt++)
#pragma unroll
            for (int r = 0; r < 4; r++) acc[mt][nt][r] = 0.f;

    const uint32_t lane_a = (uint32_t)((lane >> 2) * 144 + (lane & 3) * 4);

    float4 pf[8];
#pragma unroll
    for (int it = 0; it < 8; it++) {
        int fl = t + 256 * it;
        pf[it] = *(const float4*)(Xb + (fl >> 4) * DD + (fl & 15) * 4);
    }
#pragma unroll
    for (int it = 0; it < 8; it++) {
        int fl = t + 256 * it;
        int r = fl >> 4, c4 = fl & 15;
        uint32_t h01, h23, l01, l23;
        bf16_split4(pf[it], h01, h23, l01, l23);
        uint32_t off = (uint32_t)(r * 144 + c4 * 8);
        asm volatile("st.shared.v2.b32 [%0], {%1,%2};"
                     :: "r"(sb + off), "r"(h01), "r"(h23) : "memory");
        asm volatile("st.shared.v2.b32 [%0], {%1,%2};"
                     :: "r"(sb + TILE_B + off), "r"(l01), "r"(l23) : "memory");
    }
    __syncthreads();

    for (int ch = 0; ch < 16; ch++) {
        const uint32_t hi_s = sb + (uint32_t)(ch & 1) * (2 * TILE_B);
        const uint32_t lo_s = hi_s + TILE_B;
        if (ch + 1 < 16) {
#pragma unroll
            for (int it = 0; it < 8; it++) {
                int fl = t + 256 * it;
                pf[it] = *(const float4*)(Xb + (fl >> 4) * DD + (ch + 1) * 64 + (fl & 15) * 4);
            }
        }

#pragma unroll
        for (int ks = 0; ks < 4; ks++) {
            const uint32_t kb = (uint32_t)(ks * 32);
            uint32_t Ah[4][4], Al[4][4], Bh[4][2], Bl[4][2];
#pragma unroll
            for (int mt = 0; mt < 4; mt++) {
                if (96 + 8 * wq >= 32 * mt + 16 * wp) {
                    int m0 = 16 * (2 * mt + wp);
                    uint32_t ah = hi_s + (uint32_t)(m0 * 144) + kb + lane_a;
                    uint32_t al = lo_s + (uint32_t)(m0 * 144) + kb + lane_a;
                    asm volatile("ld.shared.b32 %0, [%1];"       : "=r"(Ah[mt][0]) : "r"(ah));
                    asm volatile("ld.shared.b32 %0, [%1+1152];"  : "=r"(Ah[mt][1]) : "r"(ah));
                    asm volatile("ld.shared.b32 %0, [%1+16];"    : "=r"(Ah[mt][2]) : "r"(ah));
                    asm volatile("ld.shared.b32 %0, [%1+1168];"  : "=r"(Ah[mt][3]) : "r"(ah));
                    asm volatile("ld.shared.b32 %0, [%1];"       : "=r"(Al[mt][0]) : "r"(al));
                    asm volatile("ld.shared.b32 %0, [%1+1152];"  : "=r"(Al[mt][1]) : "r"(al));
                    asm volatile("ld.shared.b32 %0, [%1+16];"    : "=r"(Al[mt][2]) : "r"(al));
                    asm volatile("ld.shared.b32 %0, [%1+1168];"  : "=r"(Al[mt][3]) : "r"(al));
                }
            }
#pragma unroll
            for (int nt = 0; nt < 4; nt++) {
                if (32 * nt + 8 * wq >= 16 * wp) {
                    int n0 = 32 * nt + 8 * wq;
                    uint32_t bh = hi_s + (uint32_t)(n0 * 144) + kb + lane_a;
                    uint32_t bl = lo_s + (uint32_t)(n0 * 144) + kb + lane_a;
                    asm volatile("ld.shared.b32 %0, [%1];"    : "=r"(Bh[nt][0]) : "r"(bh));
                    asm volatile("ld.shared.b32 %0, [%1+16];" : "=r"(Bh[nt][1]) : "r"(bh));
                    asm volatile("ld.shared.b32 %0, [%1];"    : "=r"(Bl[nt][0]) : "r"(bl));
                    asm volatile("ld.shared.b32 %0, [%1+16];" : "=r"(Bl[nt][1]) : "r"(bl));
                }
            }
#pragma unroll
            for (int mt = 0; mt < 4; mt++)
#pragma unroll
                for (int nt = 0; nt < 4; nt++) {
                    if (32 * nt + 8 * wq >= 32 * mt + 16 * wp) {
                        mma_bf16(acc[mt][nt], Ah[mt][0], Ah[mt][1], Ah[mt][2], Ah[mt][3],
                                 Bh[nt][0], Bh[nt][1]);
                        mma_bf16(acc[mt][nt], Ah[mt][0], Ah[mt][1], Ah[mt][2], Ah[mt][3],
                                 Bl[nt][0], Bl[nt][1]);
                        mma_bf16(acc[mt][nt], Al[mt][0], Al[mt][1], Al[mt][2], Al[mt][3],
                                 Bh[nt][0], Bh[nt][1]);
                    }
                }
        }

        if (ch + 1 < 16) {
            const uint32_t nhi = sb + (uint32_t)((ch + 1) & 1) * (2 * TILE_B);
            const uint32_t nlo = nhi + TILE_B;
#pragma unroll
            for (int it = 0; it < 8; it++) {
                int fl = t + 256 * it;
                int r = fl >> 4, c4 = fl & 15;
                uint32_t h01, h23, l01, l23;
                bf16_split4(pf[it], h01, h23, l01, l23);
                uint32_t off = (uint32_t)(r * 144 + c4 * 8);
                asm volatile("st.shared.v2.b32 [%0], {%1,%2};"
                             :: "r"(nhi + off), "r"(h01), "r"(h23) : "memory");
                asm volatile("st.shared.v2.b32 [%0], {%1,%2};"
                             :: "r"(nlo + off), "r"(l01), "r"(l23) : "memory");
            }
        }
        __syncthreads();
    }

    float* Gb = g_G + (size_t)bc * (NV * NV);
#pragma unroll
    for (int mt = 0; mt < 4; mt++)
#pragma unroll
        for (int nt = 0; nt < 4; nt++) {
            if (32 * nt + 8 * wq >= 32 * mt + 16 * wp) {
                int row = 16 * (2 * mt + wp) + (lane >> 2);
                int col = 32 * nt + 8 * wq + (lane & 3) * 2;
#pragma unroll
                for (int e = 0; e < 4; e++) {
                    int r = row + (e >> 1) * 8;
                    int c = col + (e & 1);
                    float v = acc[mt][nt][e];
                    if (c >= r) Gb[r * NV + c] = v;
                    if (c > r)  Gb[c * NV + r] = v;
                }
            }
        }
}

// ---------------------------------------------------------------- kernel B
// Blocked (16-row panel) triangular-overlay recurrence.
__global__ void gs_chol_kernel() {
    extern __shared__ float M[];                // 128 x 129
    float* cfA  = M + NV * 129;                 // 128 x CFS (float4-aligned rows)
    float* cf0  = cfA + NV * CFS;               // 4 x 128
    float* cf1v = cf0 + NV;
    float* cf2v = cf1v + NV;
    float* cf3v = cf2v + NV;
    float* pub  = cf3v + NV;                    // 16

    const int bc = blockIdx.x;
    const int t  = threadIdx.x;
    const float* Gb = g_G + (size_t)bc * (NV * NV);

#pragma unroll
    for (int it = 0; it < 129; it++) M[it * 128 + t] = 0.f;
    cf0[t] = 0.f; cf1v[t] = 0.f; cf2v[t] = 0.f; cf3v[t] = 0.f;
    __syncthreads();

    float invnn = 1.f;
    // row 0
    float g0 = Gb[t];
    M[t] = g0;
    if (t == 0) invnn = 1.f / g0;
    __syncthreads();
    // row 1
    {
        float g1 = Gb[NV + t];
        if (t == 0) pub[0] = M[1] * invnn;
        __syncthreads();
        float cf = pub[0];
        float v = (t >= 1) ? (g1 - cf * M[t]) : -cf;
        M[129 + t] = v;
        if (t == 1) invnn = 1.f / v;
        __syncthreads();
    }
    // pair i=2
    {
        const int i = 2;
        float g1 = Gb[i * NV + t];
        float g2 = Gb[(i + 1) * NV + t];
        float c1 = (t < i) ? M[t * 129 + i] * invnn : 0.f;
        float c2 = (t < i) ? M[t * 129 + i + 1] * invnn : 0.f;
        cf0[t] = c1; cf1v[t] = c2;
        __syncthreads();

        float a1 = (t >= i) ? g1 : -c1;
        float a2 = (t > i)  ? g2 : ((t == i) ? 0.f : -c2);
        for (int j = 0; j < i; j++) {
            float m = M[j * 129 + t];
            float f1 = ((t >= i) || (j > t)) ? cf0[j] : 0.f;
            float f2 = ((t > i)  || (j > t)) ? cf1v[j] : 0.f;
            a1 -= f1 * m;
            a2 -= f2 * m;
        }
        M[i * 129 + t] = a1;
        if (t == i)     { invnn = 1.f / a1; pub[0] = invnn; }
        if (t == i + 1) { pub[1] = a1; }
        __syncthreads();
        float cf2i = pub[1] * pub[0];
        a2 -= cf2i * ((t == i) ? 1.f : a1);
        M[(i + 1) * 129 + t] = a2;
        if (t == i + 1) invnn = 1.f / a2;
        __syncthreads();
    }

    // panel 0 remaining blocks i = 4, 8, 12 (C = 0): j < i <= 12
    for (int i = 4; i < 16; i += 4) {
        float gg0 = Gb[(i + 0) * NV + t];
        float gg1 = Gb[(i + 1) * NV + t];
        float gg2 = Gb[(i + 2) * NV + t];
        float gg3 = Gb[(i + 3) * NV + t];

        float c0 = 0.f, c1 = 0.f, c2 = 0.f, c3 = 0.f;
        if (t < i) {
            const float* Mr = M + t * 129 + i;
            c0 = Mr[0] * invnn; c1 = Mr[1] * invnn;
            c2 = Mr[2] * invnn; c3 = Mr[3] * invnn;
        }
        cf0[t] = c0; cf1v[t] = c1; cf2v[t] = c2; cf3v[t] = c3;
        __syncthreads();

        float a0 = (t >= i)     ? gg0 : -c0;
        float a1 = (t >= i + 1) ? gg1 : ((t >= i) ? 0.f : -c1);
        float a2 = (t >= i + 2) ? gg2 : ((t >= i) ? 0.f : -c2);
        float a3 = (t >= i + 3) ? gg3 : ((t >= i) ? 0.f : -c3);
        for (int j = 0; j < i; j++) {
            float m = M[j * 129 + t];
            bool jt = (j > t);
            a0 -= (((t >= i)     || jt) ? cf0[j]  : 0.f) * m;
            a1 -= (((t >= i + 1) || jt) ? cf1v[j] : 0.f) * m;
            a2 -= (((t >= i + 2) || jt) ? cf2v[j] : 0.f) * m;
            a3 -= (((t >= i + 3) || jt) ? cf3v[j] : 0.f) * m;
        }

        if (t == i)     { invnn = 1.f / a0; pub[0] = invnn; }
        if (t == i + 1) pub[3] = a0;
        if (t == i + 2) pub[4] = a0;
        if (t == i + 3) pub[5] = a0;
        __syncthreads();
        { float cf = pub[3] * pub[0]; a1 -= cf * ((t == i) ? 1.f : a0); }
        if (t == i + 1) { invnn = 1.f / a1; pub[1] = invnn; }
        if (t == i + 2) pub[6] = a1;
        if (t == i + 3) pub[7] = a1;
        __syncthreads();
        {
            float cf20 = pub[4] * pub[0];
            float cf21 = pub[6] * pub[1];
            float m0 = (t == i) ? 1.f : ((t == i + 1) ? 0.f : a0);
            float m1 = (t == i + 1) ? 1.f : a1;
            a2 -= cf20 * m0 + cf21 * m1;
        }
        if (t == i + 2) { invnn = 1.f / a2; pub[2] = invnn; }
        if (t == i + 3) pub[8] = a2;
        __syncthreads();
        {
            float cf30 = pub[5] * pub[0];
            float cf31 = pub[7] * pub[1];
            float cf32 = pub[8] * pub[2];
            float m0 = (t == i) ? 1.f : ((t == i + 1 || t == i + 2) ? 0.f : a0);
            float m1 = (t == i + 1) ? 1.f : ((t == i + 2) ? 0.f : a1);
            float m2 = (t == i + 2) ? 1.f : a2;
            a3 -= cf30 * m0 + cf31 * m1 + cf32 * m2;
        }
        if (t == i + 3) invnn = 1.f / a3;

        M[(i + 0) * 129 + t] = a0;
        M[(i + 1) * 129 + t] = a1;
        M[(i + 2) * 129 + t] = a2;
        M[(i + 3) * 129 + t] = a3;
        __syncthreads();
    }

    // panels 1..7
    for (int p = 1; p < 8; p++) {
        const int i0 = p * 16;

        // stage cfA: thread j < i0 writes its 16 coefs
        if (t < i0) {
            const float* Mr = M + t * 129 + i0;
            float* ca = cfA + t * CFS;
#pragma unroll
            for (int k4 = 0; k4 < 4; k4++) {
                ca[k4 * 4 + 0] = Mr[k4 * 4 + 0] * invnn;
                ca[k4 * 4 + 1] = Mr[k4 * 4 + 1] * invnn;
                ca[k4 * 4 + 2] = Mr[k4 * 4 + 2] * invnn;
                ca[k4 * 4 + 3] = Mr[k4 * 4 + 3] * invnn;
            }
        }
        __syncthreads();

        // per-thread GEMM: Cp[k] = sum_{j<i0} mask cfA[j][k] M[j][t]
        float Cp[16];
#pragma unroll
        for (int k = 0; k < 16; k++) Cp[k] = 0.f;
        const bool tP = (t >= i0);
#pragma unroll 2
        for (int j = 0; j < i0; j++) {
            float m = M[j * 129 + t];
            float mm = (tP || (j > t)) ? m : 0.f;
            const float* ca = cfA + j * CFS;
            float4 f0 = *(const float4*)(ca);
            float4 f1 = *(const float4*)(ca + 4);
            float4 f2 = *(const float4*)(ca + 8);
            float4 f3 = *(const float4*)(ca + 12);
            Cp[0]  += f0.x * mm; Cp[1]  += f0.y * mm; Cp[2]  += f0.z * mm; Cp[3]  += f0.w * mm;
            Cp[4]  += f1.x * mm; Cp[5]  += f1.y * mm; Cp[6]  += f1.z * mm; Cp[7]  += f1.w * mm;
            Cp[8]  += f2.x * mm; Cp[9]  += f2.y * mm; Cp[10] += f2.z * mm; Cp[11] += f2.w * mm;
            Cp[12] += f3.x * mm; Cp[13] += f3.y * mm; Cp[14] += f3.z * mm; Cp[15] += f3.w * mm;
        }
        if (t < i0) {
            const float* ca = cfA + t * CFS;
#pragma unroll
            for (int k = 0; k < 16; k++) Cp[k] += ca[k];
        }

        // 4 sub-blocks
#pragma unroll
        for (int s = 0; s < 4; s++) {
            const int r0 = i0 + 4 * s;
            float gg0 = Gb[(r0 + 0) * NV + t];
            float gg1 = Gb[(r0 + 1) * NV + t];
            float gg2 = Gb[(r0 + 2) * NV + t];
            float gg3 = Gb[(r0 + 3) * NV + t];

            float c0 = 0.f, c1 = 0.f, c2 = 0.f, c3 = 0.f;
            if (t >= i0 && t < r0) {
                const float* Mr = M + t * 129 + r0;
                c0 = Mr[0] * invnn; c1 = Mr[1] * invnn;
                c2 = Mr[2] * invnn; c3 = Mr[3] * invnn;
            }
            cf0[t] = c0; cf1v[t] = c1; cf2v[t] = c2; cf3v[t] = c3;
            __syncthreads();

            const bool tLo = (t < i0);
            float a0 = (t >= r0)     ? gg0 : -c0;
            float a1 = (t >= r0 + 1) ? gg1 : ((t >= r0) ? 0.f : -c1);
            float a2 = (t >= r0 + 2) ? gg2 : ((t >= r0) ? 0.f : -c2);
            float a3 = (t >= r0 + 3) ? gg3 : ((t >= r0) ? 0.f : -c3);
            a0 -= ((t >= r0)     || tLo) ? Cp[4 * s + 0] : 0.f;
            a1 -= ((t >= r0 + 1) || tLo) ? Cp[4 * s + 1] : 0.f;
            a2 -= ((t >= r0 + 2) || tLo) ? Cp[4 * s + 2] : 0.f;
            a3 -= ((t >= r0 + 3) || tLo) ? Cp[4 * s + 3] : 0.f;

            for (int j = i0; j < r0; j++) {
                float m = M[j * 129 + t];
                bool jt = (j > t);
                a0 -= (((t >= r0)     || jt) ? cf0[j]  : 0.f) * m;
                a1 -= (((t >= r0 + 1) || jt) ? cf1v[j] : 0.f) * m;
                a2 -= (((t >= r0 + 2) || jt) ? cf2v[j] : 0.f) * m;
                a3 -= (((t >= r0 + 3) || jt) ? cf3v[j] : 0.f) * m;
            }

            if (t == r0)     { invnn = 1.f / a0; pub[0] = invnn; }
            if (t == r0 + 1) pub[3] = a0;
            if (t == r0 + 2) pub[4] = a0;
            if (t == r0 + 3) pub[5] = a0;
            __syncthreads();
            { float cf = pub[3] * pub[0]; a1 -= cf * ((t == r0) ? 1.f : a0); }
            if (t == r0 + 1) { invnn = 1.f / a1; pub[1] = invnn; }
            if (t == r0 + 2) pub[6] = a1;
            if (t == r0 + 3) pub[7] = a1;
            __syncthreads();
            {
                float cf20 = pub[4] * pub[0];
                float cf21 = pub[6] * pub[1];
                float m0 = (t == r0) ? 1.f : ((t == r0 + 1) ? 0.f : a0);
                float m1 = (t == r0 + 1) ? 1.f : a1;
                a2 -= cf20 * m0 + cf21 * m1;
            }
            if (t == r0 + 2) { invnn = 1.f / a2; pub[2] = invnn; }
            if (t == r0 + 3) pub[8] = a2;
            __syncthreads();
            {
                float cf30 = pub[5] * pub[0];
                float cf31 = pub[7] * pub[1];
                float cf32 = pub[8] * pub[2];
                float m0 = (t == r0) ? 1.f : ((t == r0 + 1 || t == r0 + 2) ? 0.f : a0);
                float m1 = (t == r0 + 1) ? 1.f : ((t == r0 + 2) ? 0.f : a1);
                float m2 = (t == r0 + 2) ? 1.f : a2;
                a3 -= cf30 * m0 + cf31 * m1 + cf32 * m2;
            }
            if (t == r0 + 3) invnn = 1.f / a3;

            M[(r0 + 0) * 129 + t] = a0;
            M[(r0 + 1) * 129 + t] = a1;
            M[(r0 + 2) * 129 + t] = a2;
            M[(r0 + 3) * 129 + t] = a3;
            __syncthreads();
        }
    }

    float* Lb = g_L + (size_t)bc * (NV * NV);
#pragma unroll 4
    for (int r = 0; r < NV; r++) {
        float v = (t < r) ? M[r * 129 + t] : ((t == r) ? 1.f : 0.f);
        Lb[r * NV + t] = v;
    }
}

// ---------------------------------------------------------------- kernel C
// (R11 version — known good)
#define LT 18432
#define XT 17408
__global__ void __launch_bounds__(256) gs_apply_mma(const float* __restrict__ X,
                                                   float* __restrict__ out) {
    extern __shared__ __align__(16) char smc[];
    const int bc = blockIdx.x >> 3;
    const int dc = blockIdx.x & 7;
    const int t = threadIdx.x, lane = t & 31, wid = t >> 5;
    const int wp = wid >> 2;
    const int wn = (wid & 3) * 32;
    const uint32_t sb = smem_u32(smc);
    const uint32_t Lh = sb, Ll = sb + LT, Xh = sb + 2 * LT, Xl = sb + 2 * LT + XT;

    const float* Xb = X + (size_t)bc * (NV * DD) + dc * 128;
    const float* Lb = g_L + (size_t)bc * (NV * NV);

    float acc[4][4][4];
#pragma unroll
    for (int mt = 0; mt < 4; mt++)
#pragma unroll
        for (int nt = 0; nt < 4; nt++)
#pragma unroll
            for (int r = 0; r < 4; r++) acc[mt][nt][r] = 0.f;

    const uint32_t lane_a = (uint32_t)((lane >> 2) * 144 + (lane & 3) * 4);
    const int brow = (lane & 7) + (lane & 8);
    const int bcol = wn + ((lane >> 4) << 3);

    for (int ch = 0; ch < 2; ch++) {
#pragma unroll
        for (int it = 0; it < 8; it++) {
            int fl = t + 256 * it;
            int r = fl >> 4, c4 = fl & 15;
            float4 v = *(const float4*)(Lb + r * NV + ch * 64 + c4 * 4);
            uint32_t h01, h23, l01, l23;
            bf16_split4(v, h01, h23, l01, l23);
            uint32_t off = (uint32_t)(r * 144 + c4 * 8);
            asm volatile("st.shared.v2.b32 [%0], {%1,%2};"
                         :: "r"(Lh + off), "r"(h01), "r"(h23) : "memory");
            asm volatile("st.shared.v2.b32 [%0], {%1,%2};"
                         :: "r"(Ll + off), "r"(l01), "r"(l23) : "memory");
        }
#pragma unroll
        for (int it = 0; it < 8; it++) {
            int fl = t + 256 * it;
            int r = fl >> 5, c4 = fl & 31;
            float4 v = *(const float4*)(Xb + (ch * 64 + r) * DD + c4 * 4);
            uint32_t h01, h23, l01, l23;
            bf16_split4(v, h01, h23, l01, l23);
            uint32_t off = (uint32_t)(r * 272 + c4 * 8);
            asm volatile("st.shared.v2.b32 [%0], {%1,%2};"
                         :: "r"(Xh + off), "r"(h01), "r"(h23) : "memory");
            asm volatile("st.shared.v2.b32 [%0], {%1,%2};"
                         :: "r"(Xl + off), "r"(l01), "r"(l23) : "memory");
        }
        __syncthreads();

#pragma unroll
        for (int ks = 0; ks < 4; ks++) {
            const int kg = ch * 4 + ks;
            uint32_t Bh[4][2], Bl[4][2];
#pragma unroll
            for (int nb2 = 0; nb2 < 2; nb2++) {
                uint32_t ba = (uint32_t)((ks * 16 + brow) * 272 + (bcol + nb2 * 16) * 2);
                uint32_t r0, r1, r2, r3;
                asm volatile("ldmatrix.sync.aligned.m8n8.x4.trans.shared.b16 "
                             "{%0,%1,%2,%3}, [%4];"
                             : "=r"(r0), "=r"(r1), "=r"(r2), "=r"(r3) : "r"(Xh + ba));
                Bh[nb2 * 2][0] = r0; Bh[nb2 * 2][1] = r1;
                Bh[nb2 * 2 + 1][0] = r2; Bh[nb2 * 2 + 1][1] = r3;
                asm volatile("ldmatrix.sync.aligned.m8n8.x4.trans.shared.b16 "
                             "{%0,%1,%2,%3}, [%4];"
                             : "=r"(r0), "=r"(r1), "=r"(r2), "=r"(r3) : "r"(Xl + ba));
                Bl[nb2 * 2][0] = r0; Bl[nb2 * 2][1] = r1;
                Bl[nb2 * 2 + 1][0] = r2; Bl[nb2 * 2 + 1][1] = r3;
            }
#pragma unroll
            for (int mt = 0; mt < 4; mt++) {
                if (kg <= 2 * mt + wp) {
                    uint32_t ah = Lh + (uint32_t)((2 * mt + wp) * 2304 + ks * 32) + lane_a;
                    uint32_t al = Ll + (uint32_t)((2 * mt + wp) * 2304 + ks * 32) + lane_a;
                    uint32_t A0, A1, A2, A3, a0, a1, a2, a3;
                    asm volatile("ld.shared.b32 %0, [%1];"      : "=r"(A0) : "r"(ah));
                    asm volatile("ld.shared.b32 %0, [%1+1152];" : "=r"(A1) : "r"(ah));
                    asm volatile("ld.shared.b32 %0, [%1+16];"   : "=r"(A2) : "r"(ah));
                    asm volatile("ld.shared.b32 %0, [%1+1168];" : "=r"(A3) : "r"(ah));
                    asm volatile("ld.shared.b32 %0, [%1];"      : "=r"(a0) : "r"(al));
                    asm volatile("ld.shared.b32 %0, [%1+1152];" : "=r"(a1) : "r"(al));
                    asm volatile("ld.shared.b32 %0, [%1+16];"   : "=r"(a2) : "r"(al));
                    asm volatile("ld.shared.b32 %0, [%1+1168];" : "=r"(a3) : "r"(al));
#pragma unroll
                    for (int nt = 0; nt < 4; nt++) {
                        mma_bf16(acc[mt][nt], A0, A1, A2, A3, Bh[nt][0], Bh[nt][1]);
                        mma_bf16(acc[mt][nt], A0, A1, A2, A3, Bl[nt][0], Bl[nt][1]);
                        mma_bf16(acc[mt][nt], a0, a1, a2, a3, Bh[nt][0], Bh[nt][1]);
                    }
                }
            }
        }
        __syncthreads();
    }

    float* Qs = (float*)smc;
    float* rn = Qs + 128 * 132;
#pragma unroll
    for (int mt = 0; mt < 4; mt++) {
        int row = (2 * mt + wp) * 16 + (lane >> 2);
#pragma unroll
        for (int nt = 0; nt < 4; nt++) {
            int col = wn + nt * 8 + (lane & 3) * 2;
            *(float2*)(Qs + row * 132 + col)       = make_float2(acc[mt][nt][0], acc[mt][nt][1]);
            *(float2*)(Qs + (row + 8) * 132 + col) = make_float2(acc[mt][nt][2], acc[mt][nt][3]);
        }
    }
    __syncthreads();

    if (t < 128) {
        float s = 0.f;
#pragma unroll 4
        for (int i = 0; i < 128; i++) { float q = Qs[i * 132 + t]; s += q * q; }
        rn[t] = rsqrtf(s);
    }
    __syncthreads();

    float* ob = out + (size_t)bc * (NV * DD) + dc * 128;
#pragma unroll
    for (int it = 0; it < 16; it++) {
        int fl = t + 256 * it;
        int r = fl >> 5, c4 = fl & 31;
        float4 q = *(float4*)(Qs + r * 132 + c4 * 4);
        q.x *= rn[c4 * 4 + 0];
        q.y *= rn[c4 * 4 + 1];
        q.z *= rn[c4 * 4 + 2];
        q.w *= rn[c4 * 4 + 3];
        *(float4*)(ob + r * DD + c4 * 4) = q;
    }
}

// ---------------------------------------------------------------- launcher
extern "C" void kernel_launch(void* const* d_in, const int* in_sizes, int n_in,
                              void* d_out, int out_size) {
    const float* x = (const float*)d_in[0];
    float* out = (float*)d_out;

    const int smA = 4 * TILE_B;                                              // 73728
    const int smB = (NV * 129 + NV * CFS + 4 * NV + 16) * (int)sizeof(float); // 78400
    const int smC = 2 * LT + 2 * XT;                                         // 71680

    cudaFuncSetAttribute(gs_gram_mma,    cudaFuncAttributeMaxDynamicSharedMemorySize, smA);
    cudaFuncSetAttribute(gs_chol_kernel, cudaFuncAttributeMaxDynamicSharedMemorySize, smB);
    cudaFuncSetAttribute(gs_apply_mma,   cudaFuncAttributeMaxDynamicSharedMemorySize, smC);

    gs_gram_mma<<<NBC, 256, smA>>>(x);
    gs_chol_kernel<<<NBC, 128, smB>>>();
    gs_apply_mma<<<NBC * 8, 256, smC>>>(x, out);
}